// round 3
// baseline (speedup 1.0000x reference)
#include <cuda_runtime.h>

// VectorQuantizer: x (32,64,64,64) fp32, embeddings (64,512) fp32.
// Reference (fp32, elementwise): d_k = (||x||^2 - 2*(x.e_k)) + ||e_k||^2 ; argmin
// first-index tie-break; out = x + (q - x); loss = 1.25*mean((x-q)^2).
// Critical: ||x||^2 ~ 64 quantizes d_k to ULP(64)=7.6e-6 -> exact ties are common;
// we must reproduce the reference's fp32 rounding to resolve them identically.

#define DDIM 64
#define KCODES 512
#define ESTRIDE 516            // 64x516 fp32 smem, 16B-aligned rows, gather <=4-way conflict
#define ROWS_TILE 16
#define TILES_PER_BLOCK 8
#define ROWS_PER_BLOCK (ROWS_TILE * TILES_PER_BLOCK)   // 128
#define NTHREADS 256
#define MAX_BLOCKS 4096

// smem float offsets
#define ES_OFF      0                       // 64*516 = 33024
#define ENORM_OFF   33024                   // 512
#define XS_OFF      33536                   // 16*64 = 1024
#define XNORM_OFF   34560                   // 16
#define CANDV_OFF   34576                   // 8 warps * 4 rows = 32
#define CANDK_OFF   34608                   // 32 (int)
#define CODES_OFF   34640                   // 16 (int)
#define RLOSS_OFF   34656                   // 16
#define SMEM_FLOATS 34672

__device__ double g_partial[MAX_BLOCKS];

__global__ __launch_bounds__(NTHREADS, 1)
void vq_main(const float* __restrict__ x, const float* __restrict__ emb,
             float* __restrict__ out)
{
    extern __shared__ float sm[];
    float* Es     = sm + ES_OFF;
    float* enorm  = sm + ENORM_OFF;
    float* xs     = sm + XS_OFF;
    float* xnorm  = sm + XNORM_OFF;
    float* candv  = sm + CANDV_OFF;
    int*   candk  = (int*)(sm + CANDK_OFF);
    int*   codes  = (int*)(sm + CODES_OFF);
    float* rloss  = sm + RLOSS_OFF;

    const int t = threadIdx.x;

    // ---- load embeddings [64][512] -> Es (stride 516), float4 coalesced ----
    for (int idx = t; idx < (DDIM * KCODES) / 4; idx += NTHREADS) {
        int d  = idx >> 7;        // 128 quads per row
        int kq = idx & 127;
        float4 v = ((const float4*)emb)[idx];
        *(float4*)&Es[d * ESTRIDE + kq * 4] = v;
    }
    __syncthreads();

    // ---- per-code squared norms: sequential d-ascending, mul then add (no fma),
    //      matching jnp.sum(E*E, axis=0) naive reduce order ----
    for (int k = t; k < KCODES; k += NTHREADS) {
        float s = 0.f;
        #pragma unroll
        for (int d = 0; d < DDIM; d++) {
            float e = Es[d * ESTRIDE + k];
            s = __fadd_rn(s, __fmul_rn(e, e));
        }
        enorm[k] = s;
    }
    __syncthreads();

    const int tx   = t & 63;      // code-group: codes [8*tx, 8*tx+8)
    const int ty   = t >> 6;      // row-group: rows [4*ty, 4*ty+4)
    const int k0   = tx * 8;
    const int lane = t & 31;
    const int warp = t >> 5;

    double block_loss = 0.0;
    const long row0base = (long)blockIdx.x * ROWS_PER_BLOCK;

    for (int tile = 0; tile < TILES_PER_BLOCK; tile++) {
        const long row0 = row0base + (long)tile * ROWS_TILE;

        // ---- load x tile [16][64] (coalesced float4) ----
        {
            float4 v = ((const float4*)(x + row0 * DDIM))[t];
            *(float4*)&xs[t * 4] = v;
        }
        __syncthreads();

        // ---- per-row ||x||^2: sequential d-ascending, mul then add (no fma) ----
        if (t < ROWS_TILE) {
            float s = 0.f;
            #pragma unroll
            for (int d = 0; d < DDIM; d++) {
                float v = xs[t * DDIM + d];
                s = __fadd_rn(s, __fmul_rn(v, v));
            }
            xnorm[t] = s;
        }
        __syncthreads();

        // ---- register-tiled GEMM: 4 rows x 8 codes per thread,
        //      sequential single-accumulator fma chain over d (matches GEMM k-loop) ----
        float acc[4][8];
        #pragma unroll
        for (int i = 0; i < 4; i++)
            #pragma unroll
            for (int j = 0; j < 8; j++) acc[i][j] = 0.f;

        #pragma unroll 4
        for (int d = 0; d < DDIM; d++) {
            float4 e0 = *(float4*)&Es[d * ESTRIDE + k0];
            float4 e1 = *(float4*)&Es[d * ESTRIDE + k0 + 4];
            float ev[8] = {e0.x, e0.y, e0.z, e0.w, e1.x, e1.y, e1.z, e1.w};
            float xv[4];
            #pragma unroll
            for (int i = 0; i < 4; i++) xv[i] = xs[(ty * 4 + i) * 64 + d];
            #pragma unroll
            for (int i = 0; i < 4; i++)
                #pragma unroll
                for (int j = 0; j < 8; j++)
                    acc[i][j] = fmaf(xv[i], ev[j], acc[i][j]);
        }

        // ---- per-thread argmin: d_k = (xn - 2*m) + en, reference fp32 rounding ----
        float bv[4]; int bk[4];
        #pragma unroll
        for (int i = 0; i < 4; i++) {
            float xnv = xnorm[ty * 4 + i];
            bv[i] = 3.402823466e38f; bk[i] = 0;
            #pragma unroll
            for (int j = 0; j < 8; j++) {
                float s = __fadd_rn(__fsub_rn(xnv, 2.0f * acc[i][j]), enorm[k0 + j]);
                if (s < bv[i]) { bv[i] = s; bk[i] = k0 + j; }   // ascending k: first-min kept
            }
        }

        // ---- warp argmin reduce (prefer lower k on tie) ----
        #pragma unroll
        for (int i = 0; i < 4; i++) {
            float v = bv[i]; int kk = bk[i];
            #pragma unroll
            for (int ofs = 16; ofs > 0; ofs >>= 1) {
                float ov = __shfl_xor_sync(0xffffffffu, v, ofs);
                int   ok = __shfl_xor_sync(0xffffffffu, kk, ofs);
                if (ov < v || (ov == v && ok < kk)) { v = ov; kk = ok; }
            }
            if (lane == 0) { candv[warp * 4 + i] = v; candk[warp * 4 + i] = kk; }
        }
        __syncthreads();

        // ---- merge the 2 warp-candidates per row, emit code + loss term ----
        if (t < ROWS_TILE) {
            int r = t;
            int wa = (r >> 2) * 2, i = r & 3;
            float v0 = candv[wa * 4 + i];       int c0 = candk[wa * 4 + i];
            float v1 = candv[(wa + 1) * 4 + i]; int c1 = candk[(wa + 1) * 4 + i];
            float v; int c;
            if (v1 < v0 || (v1 == v0 && c1 < c0)) { v = v1; c = c1; }
            else                                   { v = v0; c = c0; }
            codes[r] = c;
            rloss[r] = v;    // d_min = ||x - e||^2 with reference rounding
        }
        __syncthreads();

        // ---- write quantized rows with straight-through rounding:
        //      out = fl(x + fl(q - x)) ----
        #pragma unroll
        for (int rep = 0; rep < 4; rep++) {
            int idx = rep * NTHREADS + t;
            int i = idx >> 6, d = idx & 63;
            float q  = Es[d * ESTRIDE + codes[i]];
            float xv = xs[idx];
            out[row0 * DDIM + idx] = __fadd_rn(xv, __fsub_rn(q, xv));
        }

        if (t == 0) {
            #pragma unroll
            for (int r = 0; r < ROWS_TILE; r++) block_loss += (double)rloss[r];
        }
        __syncthreads();   // protect xs reuse next tile
    }

    if (t == 0) g_partial[blockIdx.x] = block_loss;
}

__global__ void vq_finalize(float* loss_out, long n_elems, int nblocks)
{
    __shared__ double s[256];
    int t = threadIdx.x;
    double v = 0.0;
    for (int i = t; i < nblocks; i += 256) v += g_partial[i];
    s[t] = v;
    __syncthreads();
    for (int ofs = 128; ofs > 0; ofs >>= 1) {
        if (t < ofs) s[t] += s[t + ofs];
        __syncthreads();
    }
    if (t == 0) *loss_out = (float)(s[0] * 1.25 / (double)n_elems);
}

extern "C" void kernel_launch(void* const* d_in, const int* in_sizes, int n_in,
                              void* d_out, int out_size)
{
    const float* x   = (const float*)d_in[0];
    const float* emb = (const float*)d_in[1];
    float* out = (float*)d_out;

    long n    = (long)in_sizes[0];          // 8388608
    int  rows = (int)(n / DDIM);            // 131072
    int  nblocks = rows / ROWS_PER_BLOCK;   // 1024
    if (nblocks > MAX_BLOCKS) nblocks = MAX_BLOCKS;

    size_t smem = SMEM_FLOATS * sizeof(float);   // ~138.7 KB
    cudaFuncSetAttribute(vq_main, cudaFuncAttributeMaxDynamicSharedMemorySize, (int)smem);

    vq_main<<<nblocks, NTHREADS, smem>>>(x, emb, out);

    if ((long)out_size > n) {
        // loss scalar lives right after the quantized tensor
        vq_finalize<<<1, 256>>>(out + n, n, nblocks);
    }
}

// round 6
// speedup vs baseline: 1.1517x; 1.1517x over previous
#include <cuda_runtime.h>

// VectorQuantizer: x (32,64,64,64) fp32, embeddings (64,512) fp32.
// d_k = (||x||^2 - 2*(x.e_k)) + ||e_k||^2 with reference fp32 rounding; argmin
// first-index tie-break; out = q; loss = 1.25*mean(d_min).
// Numerics contract (validated rel_err==0.0 in R3): dot = sequential d-ascending
// fma chain; norms = sequential mul-then-add; distance formula elementwise fp32.
// f32x2 packed FMA keeps each lane an exact fp32 fma chain -> bitwise identical.

#define DDIM 64
#define KCODES 512
#define ESTRIDE 516            // Es row stride (floats): float4-aligned
#define XSTRIDE 68             // xs row stride: 4-way max conflict on column walk
#define ROWS_TILE 32
#define NTHREADS 512
#define MAX_BLOCKS 4096

// smem float offsets
#define ES_OFF      0                       // 64*516 = 33024
#define ENORM_OFF   33024                   // 512
#define XS_OFF      33536                   // 32*68 = 2176
#define XNORM_OFF   35712                   // 32
#define CANDV_OFF   35744                   // 16 warps * 8 rows = 128
#define CANDK_OFF   35872                   // 128 (int)
#define CODES_OFF   36000                   // 32 (int)
#define SMEM_FLOATS 36032                   // ~140.75 KB

typedef unsigned long long u64;

__device__ double g_partial[MAX_BLOCKS];

__device__ __forceinline__ void fma2(u64 &d, u64 a, u64 b) {
    asm("fma.rn.f32x2 %0, %1, %2, %0;" : "+l"(d) : "l"(a), "l"(b));
}
__device__ __forceinline__ u64 pack2(float v) {
    u64 r; asm("mov.b64 %0, {%1, %2};" : "=l"(r) : "f"(v), "f"(v)); return r;
}
__device__ __forceinline__ void unpack2(u64 v, float &lo, float &hi) {
    asm("mov.b64 {%0, %1}, %2;" : "=f"(lo), "=f"(hi) : "l"(v));
}

__global__ __launch_bounds__(NTHREADS, 1)
void vq_main(const float* __restrict__ x, const float* __restrict__ emb,
             float* __restrict__ out, int ntiles)
{
    extern __shared__ float sm[];
    float* Es     = sm + ES_OFF;
    float* enorm  = sm + ENORM_OFF;
    float* xs     = sm + XS_OFF;
    float* xnorm  = sm + XNORM_OFF;
    float* candv  = sm + CANDV_OFF;
    int*   candk  = (int*)(sm + CANDK_OFF);
    int*   codes  = (int*)(sm + CODES_OFF);

    const int t    = threadIdx.x;
    const int lane = t & 31;
    const int warp = t >> 5;
    const int tx   = t & 127;          // code group: 4 codes [4*tx, 4*tx+4)
    const int ty   = t >> 7;           // row group: 8 rows [8*ty, 8*ty+8)
    const int k0   = tx * 4;
    const int stride = gridDim.x;

    long tile = blockIdx.x;

    // ---- prologue: embeddings -> smem (stride 516), first x tile -> smem ----
    for (int idx = t; idx < (DDIM * KCODES) / 4; idx += NTHREADS) {
        int d  = idx >> 7;
        int kq = idx & 127;
        float4 v = ((const float4*)emb)[idx];
        *(float4*)&Es[d * ESTRIDE + kq * 4] = v;
    }
    {
        int r = t >> 4, c = (t & 15) * 4;
        if (tile < ntiles) {
            float4 v = ((const float4*)(x + tile * (ROWS_TILE * DDIM)))[t];
            *(float4*)&xs[r * XSTRIDE + c] = v;
        }
    }
    __syncthreads();

    // ---- per-code norms: sequential d-ascending mul-then-add (ref order) ----
    for (int k = t; k < KCODES; k += NTHREADS) {
        float s = 0.f;
        #pragma unroll
        for (int d = 0; d < DDIM; d++) {
            float e = Es[d * ESTRIDE + k];
            s = __fadd_rn(s, __fmul_rn(e, e));
        }
        enorm[k] = s;
    }
    __syncthreads();

    // this thread's 4 code norms are loop-invariant
    float en[4];
    #pragma unroll
    for (int j = 0; j < 4; j++) en[j] = enorm[k0 + j];

    double lossacc = 0.0;

    for (; tile < ntiles; tile += stride) {
        // ---- warp 0: per-row ||x||^2, sequential mul-then-add (ref order) ----
        if (t < ROWS_TILE) {
            float s = 0.f;
            #pragma unroll
            for (int d = 0; d < DDIM; d++) {
                float v = xs[t * XSTRIDE + d];
                s = __fadd_rn(s, __fmul_rn(v, v));
            }
            xnorm[t] = s;
        }

        // ---- prefetch next x tile into registers (hidden under gemm) ----
        long nxt = tile + stride;
        bool has = nxt < ntiles;
        float4 rn;
        if (has) rn = ((const float4*)(x + nxt * (ROWS_TILE * DDIM)))[t];

        // ---- f32x2 GEMM: 8 rows x 2 code-pairs per thread, d-ascending chain ----
        u64 acc[8][2];
        #pragma unroll
        for (int i = 0; i < 8; i++) { acc[i][0] = 0ull; acc[i][1] = 0ull; }

        #pragma unroll 4
        for (int d = 0; d < DDIM; d += 2) {
            ulonglong2 e0 = *(const ulonglong2*)&Es[d * ESTRIDE + k0];
            ulonglong2 e1 = *(const ulonglong2*)&Es[(d + 1) * ESTRIDE + k0];
            #pragma unroll
            for (int i = 0; i < 8; i++) {
                float2 xv = *(const float2*)&xs[(ty * 8 + i) * XSTRIDE + d];
                u64 xa = pack2(xv.x);
                u64 xb = pack2(xv.y);
                fma2(acc[i][0], xa, e0.x);
                fma2(acc[i][1], xa, e0.y);
                fma2(acc[i][0], xb, e1.x);
                fma2(acc[i][1], xb, e1.y);
            }
        }
        __syncthreads();                        // gemm + xnorm done; xs reusable

        // ---- stage next x tile (no one reads xs until next iteration) ----
        if (has) {
            int r = t >> 4, c = (t & 15) * 4;
            *(float4*)&xs[r * XSTRIDE + c] = rn;
        }

        // ---- per-thread argmin with reference rounding, then warp reduce ----
        #pragma unroll
        for (int i = 0; i < 8; i++) {
            float m0, m1, m2, m3;
            unpack2(acc[i][0], m0, m1);
            unpack2(acc[i][1], m2, m3);
            float xnv = xnorm[ty * 8 + i];
            float s0 = __fadd_rn(__fsub_rn(xnv, 2.0f * m0), en[0]);
            float s1 = __fadd_rn(__fsub_rn(xnv, 2.0f * m1), en[1]);
            float s2 = __fadd_rn(__fsub_rn(xnv, 2.0f * m2), en[2]);
            float s3 = __fadd_rn(__fsub_rn(xnv, 2.0f * m3), en[3]);
            float bv = s0; int bk = k0;
            if (s1 < bv) { bv = s1; bk = k0 + 1; }
            if (s2 < bv) { bv = s2; bk = k0 + 2; }
            if (s3 < bv) { bv = s3; bk = k0 + 3; }
            // warp argmin (prefer lower k on tie)
            #pragma unroll
            for (int ofs = 16; ofs > 0; ofs >>= 1) {
                float ov = __shfl_xor_sync(0xffffffffu, bv, ofs);
                int   ok = __shfl_xor_sync(0xffffffffu, bk, ofs);
                if (ov < bv || (ov == bv && ok < bk)) { bv = ov; bk = ok; }
            }
            if (lane == 0) { candv[warp * 8 + i] = bv; candk[warp * 8 + i] = bk; }
        }
        __syncthreads();                        // candidates + staged xs ready

        // ---- merge 4 warp-candidates per row (ascending code blocks) ----
        if (t < ROWS_TILE) {
            int r = t;
            int wbase = (r >> 3) * 4, i = r & 7;
            float bv = candv[wbase * 8 + i]; int bk = candk[wbase * 8 + i];
            #pragma unroll
            for (int j = 1; j < 4; j++) {
                float v = candv[(wbase + j) * 8 + i];
                int   c = candk[(wbase + j) * 8 + i];
                if (v < bv) { bv = v; bk = c; }
            }
            codes[r] = bk;
            lossacc += (double)bv;              // d_min, reference rounding
        }
        __syncthreads();                        // codes ready

        // ---- write quantized rows: out[row][d] = Es[d][code] ----
        long obase = tile * (ROWS_TILE * DDIM);
        #pragma unroll
        for (int rep = 0; rep < 4; rep++) {
            int idx = rep * NTHREADS + t;
            int i = idx >> 6, d = idx & 63;
            out[obase + idx] = Es[d * ESTRIDE + codes[i]];
        }
    }

    // ---- block loss: deterministic shuffle tree over warp 0 ----
    if (warp == 0) {
        double v = lossacc;
        #pragma unroll
        for (int ofs = 16; ofs > 0; ofs >>= 1)
            v += __shfl_xor_sync(0xffffffffu, v, ofs);
        if (lane == 0) g_partial[blockIdx.x] = v;
    }
}

__global__ void vq_finalize(float* loss_out, long n_elems, int nblocks)
{
    __shared__ double s[256];
    int t = threadIdx.x;
    double v = 0.0;
    for (int i = t; i < nblocks; i += 256) v += g_partial[i];
    s[t] = v;
    __syncthreads();
    for (int ofs = 128; ofs > 0; ofs >>= 1) {
        if (t < ofs) s[t] += s[t + ofs];
        __syncthreads();
    }
    if (t == 0) *loss_out = (float)(s[0] * 1.25 / (double)n_elems);
}

extern "C" void kernel_launch(void* const* d_in, const int* in_sizes, int n_in,
                              void* d_out, int out_size)
{
    const float* x   = (const float*)d_in[0];
    const float* emb = (const float*)d_in[1];
    float* out = (float*)d_out;

    long n      = (long)in_sizes[0];            // 8388608
    int  ntiles = (int)(n / (DDIM * ROWS_TILE)); // 4096

    static int nsm = 0;
    if (nsm == 0) {
        cudaDeviceGetAttribute(&nsm, cudaDevAttrMultiProcessorCount, 0);
        if (nsm <= 0) nsm = 148;
    }
    int grid = nsm;
    if (grid > MAX_BLOCKS) grid = MAX_BLOCKS;
    if (grid > ntiles) grid = ntiles;

    size_t smem = SMEM_FLOATS * sizeof(float);
    cudaFuncSetAttribute(vq_main, cudaFuncAttributeMaxDynamicSharedMemorySize, (int)smem);

    vq_main<<<grid, NTHREADS, smem>>>(x, emb, out, ntiles);

    if ((long)out_size > n) {
        vq_finalize<<<1, 256>>>(out + n, n, grid);
    }
}

// round 7
// speedup vs baseline: 1.9613x; 1.7031x over previous
#include <cuda_runtime.h>

// VectorQuantizer: x (32,64,64,64) fp32, embeddings (64,512) fp32.
// d_k = (||x||^2 - 2*(x.e_k)) + ||e_k||^2 with reference fp32 rounding; argmin
// first-index tie-break; out = q; loss = 1.25*mean(d_min).
// Numerics contract (validated rel_err==0.0 in R3): dot = sequential d-ascending
// fma chain per (row,code); norms = sequential mul-then-add; distance formula
// elementwise fp32. f32x2 lanes hold TWO ROWS sharing one code: each lane is an
// exact fp32 fma chain -> bitwise identical to scalar.

#define DDIM 64
#define KCODES 512
#define ESTRIDE 516          // Es row stride (floats)
#define ROWS_TILE 64
#define XQS 132              // packed-x stride (floats) per d-pair; 528B = 33*16
#define NTHREADS 512
#define MAXG 256

typedef unsigned long long u64;

__device__ double g_partial[MAXG];
__device__ unsigned g_count;     // zero-init; reset by last block each launch

// smem float offsets
#define ES_OFF     0             // 64*516 = 33024
#define ENORM_OFF  33024         // 512
#define XQ_OFF     33536         // 32*132 = 4224
#define XNORM_OFF  37760         // 64
#define CANDV_OFF  37824         // 2*16*16 = 512
#define CANDK_OFF  38336         // 512 (int)
#define CODES_OFF  38848         // 64 (int)
#define RED_OFF    38912         // 512 doubles = 1024 floats (8B aligned)
#define FLAG_OFF   39936         // 1 int
#define LOSSW_OFF  39938         // 2 doubles = 4 floats (8B aligned)
#define SMEM_FLOATS 39944        // ~156 KB

__device__ __forceinline__ void fma2(u64 &d, u64 a, u64 b) {
    asm("fma.rn.f32x2 %0, %1, %2, %0;" : "+l"(d) : "l"(a), "l"(b));
}
__device__ __forceinline__ u64 pack2(float v) {
    u64 r; asm("mov.b64 %0, {%1, %2};" : "=l"(r) : "f"(v), "f"(v)); return r;
}
__device__ __forceinline__ void unpack2(u64 v, float &lo, float &hi) {
    asm("mov.b64 {%0, %1}, %2;" : "=f"(lo), "=f"(hi) : "l"(v));
}

// stage a float4 (rows-major x tile) into the packed [d/2][rowpair] layout
__device__ __forceinline__ void stage4(float* xq, int idxq, float4 v) {
    int r = idxq >> 4;
    int c = (idxq & 15) * 4;
    float vv[4] = {v.x, v.y, v.z, v.w};
    #pragma unroll
    for (int i = 0; i < 4; i++) {
        int d = c + i;
        xq[(d >> 1) * XQS + (r >> 1) * 4 + ((d & 1) << 1) + (r & 1)] = vv[i];
    }
}

__global__ __launch_bounds__(NTHREADS, 1)
void vq_main(const float* __restrict__ x, const float* __restrict__ emb,
             float* __restrict__ out, int ntiles, long nelem, int writeLoss)
{
    extern __shared__ float sm[];
    float* Es    = sm + ES_OFF;
    float* enorm = sm + ENORM_OFF;
    float* xq    = sm + XQ_OFF;
    float* xnorm = sm + XNORM_OFF;
    float* candv = sm + CANDV_OFF;
    int*   candk = (int*)(sm + CANDK_OFF);
    int*   codes = (int*)(sm + CODES_OFF);
    double* red  = (double*)(sm + RED_OFF);
    int*   flagp = (int*)(sm + FLAG_OFF);
    double* lossw= (double*)(sm + LOSSW_OFF);

    const int t    = threadIdx.x;
    const int lane = t & 31;
    const int warp = t >> 5;
    const int tx   = t & 127;        // code slot: 2 codes per pass
    const int ty   = t >> 7;         // row group: rows [16*ty, 16*ty+16)
    const int stride = gridDim.x;

    long tile = blockIdx.x;

    // ---- prologue: Es -> smem, first x tile -> packed smem ----
    for (int idx = t; idx < (DDIM * KCODES) / 4; idx += NTHREADS) {
        int d  = idx >> 7;
        int kq = idx & 127;
        float4 v = ((const float4*)emb)[idx];
        *(float4*)&Es[d * ESTRIDE + kq * 4] = v;
    }
    if (tile < ntiles) {
        const float4* p = (const float4*)(x + tile * (ROWS_TILE * DDIM));
        stage4(xq, t,       p[t]);
        stage4(xq, t + 512, p[t + 512]);
    }
    __syncthreads();

    // ---- per-code norms: sequential d-ascending mul-then-add (ref order) ----
    {
        int k = t;   // KCODES == NTHREADS
        float s = 0.f;
        #pragma unroll
        for (int d = 0; d < DDIM; d++) {
            float e = Es[d * ESTRIDE + k];
            s = __fadd_rn(s, __fmul_rn(e, e));
        }
        enorm[k] = s;
    }
    __syncthreads();

    double lossacc = 0.0;

    for (; tile < ntiles; tile += stride) {
        // ---- warps 0-1: per-row ||x||^2, sequential mul-then-add ----
        if (t < ROWS_TILE) {
            float s = 0.f;
            #pragma unroll
            for (int d = 0; d < DDIM; d++) {
                float v = xq[(d >> 1) * XQS + (t >> 1) * 4 + ((d & 1) << 1) + (t & 1)];
                s = __fadd_rn(s, __fmul_rn(v, v));
            }
            xnorm[t] = s;
        }

        // ---- prefetch next tile into registers ----
        long nxt = tile + stride;
        bool has = nxt < ntiles;
        float4 rn0, rn1;
        if (has) {
            const float4* p = (const float4*)(x + nxt * (ROWS_TILE * DDIM));
            rn0 = p[t]; rn1 = p[t + 512];
        }

        u64 acc[2][8][2];   // [pass][rowpair][code]
        #pragma unroll
        for (int p = 0; p < 2; p++)
            #pragma unroll
            for (int i = 0; i < 8; i++) { acc[p][i][0] = 0ull; acc[p][i][1] = 0ull; }

        // ================= pass 0: codes [0,256) =================
        {
            const int kp = tx * 2;
            #pragma unroll 4
            for (int dh = 0; dh < 32; dh++) {
                float2 ea = *(const float2*)&Es[(2 * dh) * ESTRIDE + kp];
                float2 eb = *(const float2*)&Es[(2 * dh + 1) * ESTRIDE + kp];
                u64 ea0 = pack2(ea.x), ea1 = pack2(ea.y);
                u64 eb0 = pack2(eb.x), eb1 = pack2(eb.y);
                const float* xb = &xq[dh * XQS + ty * 32];
                #pragma unroll
                for (int i = 0; i < 8; i++) {
                    ulonglong2 xp = *(const ulonglong2*)&xb[i * 4];
                    fma2(acc[0][i][0], xp.x, ea0);
                    fma2(acc[0][i][1], xp.x, ea1);
                    fma2(acc[0][i][0], xp.y, eb0);
                    fma2(acc[0][i][1], xp.y, eb1);
                }
            }
        }
        __syncthreads();   // xnorm ready; xq still live for pass 1

        // ---- dist + argmin pass 0 ----
        {
            const int kp = tx * 2;
            float en0 = enorm[kp], en1 = enorm[kp + 1];
            #pragma unroll
            for (int i = 0; i < 8; i++) {
                float mA0, mA1, mB0, mB1;
                unpack2(acc[0][i][0], mA0, mA1);   // code kp:   rows 2i, 2i+1
                unpack2(acc[0][i][1], mB0, mB1);   // code kp+1
                int re = ty * 16 + 2 * i;
                float xne = xnorm[re], xno = xnorm[re + 1];
                float s0e = __fadd_rn(__fsub_rn(xne, 2.0f * mA0), en0);
                float s1e = __fadd_rn(__fsub_rn(xne, 2.0f * mB0), en1);
                float s0o = __fadd_rn(__fsub_rn(xno, 2.0f * mA1), en0);
                float s1o = __fadd_rn(__fsub_rn(xno, 2.0f * mB1), en1);
                // even row
                float bv = s0e; int bk = kp;
                if (s1e < bv) { bv = s1e; bk = kp + 1; }
                unsigned mb = __reduce_min_sync(0xffffffffu, __float_as_uint(bv));
                unsigned kb = __reduce_min_sync(0xffffffffu,
                    (__float_as_uint(bv) == mb) ? (unsigned)bk : 0xffffffffu);
                if (lane == 0) {
                    candv[0 * 256 + warp * 16 + 2 * i]     = __uint_as_float(mb);
                    candk[0 * 256 + warp * 16 + 2 * i]     = (int)kb;
                }
                // odd row
                bv = s0o; bk = kp;
                if (s1o < bv) { bv = s1o; bk = kp + 1; }
                mb = __reduce_min_sync(0xffffffffu, __float_as_uint(bv));
                kb = __reduce_min_sync(0xffffffffu,
                    (__float_as_uint(bv) == mb) ? (unsigned)bk : 0xffffffffu);
                if (lane == 0) {
                    candv[0 * 256 + warp * 16 + 2 * i + 1] = __uint_as_float(mb);
                    candk[0 * 256 + warp * 16 + 2 * i + 1] = (int)kb;
                }
            }
        }

        // ================= pass 1: codes [256,512) =================
        {
            const int kp = 256 + tx * 2;
            #pragma unroll 4
            for (int dh = 0; dh < 32; dh++) {
                float2 ea = *(const float2*)&Es[(2 * dh) * ESTRIDE + kp];
                float2 eb = *(const float2*)&Es[(2 * dh + 1) * ESTRIDE + kp];
                u64 ea0 = pack2(ea.x), ea1 = pack2(ea.y);
                u64 eb0 = pack2(eb.x), eb1 = pack2(eb.y);
                const float* xb = &xq[dh * XQS + ty * 32];
                #pragma unroll
                for (int i = 0; i < 8; i++) {
                    ulonglong2 xp = *(const ulonglong2*)&xb[i * 4];
                    fma2(acc[1][i][0], xp.x, ea0);
                    fma2(acc[1][i][1], xp.x, ea1);
                    fma2(acc[1][i][0], xp.y, eb0);
                    fma2(acc[1][i][1], xp.y, eb1);
                }
            }
        }
        __syncthreads();   // all xq reads done -> safe to restage

        // ---- stage next tile into xq ----
        if (has) { stage4(xq, t, rn0); stage4(xq, t + 512, rn1); }

        // ---- dist + argmin pass 1 ----
        {
            const int kp = 256 + tx * 2;
            float en0 = enorm[kp], en1 = enorm[kp + 1];
            #pragma unroll
            for (int i = 0; i < 8; i++) {
                float mA0, mA1, mB0, mB1;
                unpack2(acc[1][i][0], mA0, mA1);
                unpack2(acc[1][i][1], mB0, mB1);
                int re = ty * 16 + 2 * i;
                float xne = xnorm[re], xno = xnorm[re + 1];
                float s0e = __fadd_rn(__fsub_rn(xne, 2.0f * mA0), en0);
                float s1e = __fadd_rn(__fsub_rn(xne, 2.0f * mB0), en1);
                float s0o = __fadd_rn(__fsub_rn(xno, 2.0f * mA1), en0);
                float s1o = __fadd_rn(__fsub_rn(xno, 2.0f * mB1), en1);
                float bv = s0e; int bk = kp;
                if (s1e < bv) { bv = s1e; bk = kp + 1; }
                unsigned mb = __reduce_min_sync(0xffffffffu, __float_as_uint(bv));
                unsigned kb = __reduce_min_sync(0xffffffffu,
                    (__float_as_uint(bv) == mb) ? (unsigned)bk : 0xffffffffu);
                if (lane == 0) {
                    candv[1 * 256 + warp * 16 + 2 * i]     = __uint_as_float(mb);
                    candk[1 * 256 + warp * 16 + 2 * i]     = (int)kb;
                }
                bv = s0o; bk = kp;
                if (s1o < bv) { bv = s1o; bk = kp + 1; }
                mb = __reduce_min_sync(0xffffffffu, __float_as_uint(bv));
                kb = __reduce_min_sync(0xffffffffu,
                    (__float_as_uint(bv) == mb) ? (unsigned)bk : 0xffffffffu);
                if (lane == 0) {
                    candv[1 * 256 + warp * 16 + 2 * i + 1] = __uint_as_float(mb);
                    candk[1 * 256 + warp * 16 + 2 * i + 1] = (int)kb;
                }
            }
        }
        __syncthreads();   // candidates + staged xq visible

        // ---- merge 8 candidates per row, ascending k blocks ----
        if (t < ROWS_TILE) {
            int r = t;
            int wb = (r >> 4) * 4, i16 = r & 15;
            float bv = candv[wb * 16 + i16];
            int   bk = candk[wb * 16 + i16];
            #pragma unroll
            for (int p = 0; p < 2; p++)
                #pragma unroll
                for (int q = 0; q < 4; q++) {
                    if (p == 0 && q == 0) continue;
                    float v = candv[p * 256 + (wb + q) * 16 + i16];
                    int   c = candk[p * 256 + (wb + q) * 16 + i16];
                    if (v < bv) { bv = v; bk = c; }
                }
            codes[r] = bk;
            lossacc += (double)bv;
        }
        __syncthreads();   // codes ready

        // ---- write quantized rows: out[row][d] = Es[d][code] ----
        long obase = tile * (ROWS_TILE * DDIM);
        #pragma unroll
        for (int rep = 0; rep < 8; rep++) {
            int idx = rep * NTHREADS + t;
            int r = idx >> 6, d = idx & 63;
            out[obase + idx] = Es[d * ESTRIDE + codes[r]];
        }
    }

    // ---- block loss: deterministic shuffle tree (warps 0,1 hold partials) ----
    if (warp < 2) {
        double v = lossacc;
        #pragma unroll
        for (int ofs = 16; ofs > 0; ofs >>= 1)
            v += __shfl_xor_sync(0xffffffffu, v, ofs);
        if (lane == 0) lossw[warp] = v;
    }
    __syncthreads();
    if (t == 0) {
        g_partial[blockIdx.x] = lossw[0] + lossw[1];
        __threadfence();
        unsigned old = atomicAdd(&g_count, 1u);
        flagp[0] = (old == gridDim.x - 1) ? 1 : 0;
    }
    __syncthreads();

    // ---- last block: deterministic fixed-order finalize ----
    if (flagp[0]) {
        volatile double* gp = g_partial;
        red[t] = (t < (int)gridDim.x) ? gp[t] : 0.0;
        __syncthreads();
        #pragma unroll
        for (int ofs = 256; ofs > 0; ofs >>= 1) {
            if (t < ofs) red[t] += red[t + ofs];
            __syncthreads();
        }
        if (t == 0) {
            if (writeLoss) out[nelem] = (float)(red[0] * 1.25 / (double)nelem);
            g_count = 0;   // reset for next launch / graph replay
        }
    }
}

extern "C" void kernel_launch(void* const* d_in, const int* in_sizes, int n_in,
                              void* d_out, int out_size)
{
    const float* x   = (const float*)d_in[0];
    const float* emb = (const float*)d_in[1];
    float* out = (float*)d_out;

    long n      = (long)in_sizes[0];              // 8388608
    int  ntiles = (int)(n / (DDIM * ROWS_TILE));  // 2048

    static int nsm = 0;
    if (nsm == 0) {
        cudaDeviceGetAttribute(&nsm, cudaDevAttrMultiProcessorCount, 0);
        if (nsm <= 0) nsm = 148;
    }
    int grid = nsm;
    if (grid > MAXG) grid = MAXG;
    if (grid > ntiles) grid = ntiles;

    size_t smem = SMEM_FLOATS * sizeof(float);
    cudaFuncSetAttribute(vq_main, cudaFuncAttributeMaxDynamicSharedMemorySize, (int)smem);

    int writeLoss = ((long)out_size > n) ? 1 : 0;
    vq_main<<<grid, NTHREADS, smem>>>(x, emb, out, ntiles, n, writeLoss);
}

// round 8
// speedup vs baseline: 2.0886x; 1.0649x over previous
#include <cuda_runtime.h>

// VectorQuantizer: x (32,64,64,64) fp32, embeddings (64,512) fp32.
// d_k = (||x||^2 - 2*(x.e_k)) + ||e_k||^2 with reference fp32 rounding; argmin
// first-index tie-break; out = q; loss = 1.25*mean(d_min).
// Numerics contract (validated rel_err==0.0 in R3): dot = sequential d-ascending
// fma chain per (row,code); norms = sequential mul-then-add; distance formula
// elementwise fp32. f32x2 lanes hold TWO ROWS sharing one code: each lane is an
// exact fp32 fma chain -> bitwise identical to scalar.

#define DDIM 64
#define KCODES 512
#define ESTRIDE 516          // Es row stride (floats)
#define ROWS_TILE 64
#define XQS 132              // packed-x stride (floats) per d-pair
#define NTHREADS 512
#define MAXG 256

typedef unsigned long long u64;

__device__ double g_partial[MAXG];
__device__ unsigned g_count;     // zero-init; reset by last block each launch

// smem float offsets
#define ES_OFF     0             // 64*516 = 33024
#define ENORM_OFF  33024         // 512
#define XQ_OFF     33536         // 32*132 = 4224
#define XNORM_OFF  37760         // 64
#define CANDV_OFF  37824         // 16 warps * 16 rows = 256
#define CANDK_OFF  38080         // 256 (int)
#define CODES_OFF  38336         // 64 (int)
#define RED_OFF    38400         // 512 doubles = 1024 floats (8B aligned)
#define FLAG_OFF   39424         // 2 ints
#define LOSSW_OFF  39426         // 2 doubles = 4 floats (8B aligned)
#define SMEM_FLOATS 39432        // ~154 KB

__device__ __forceinline__ void fma2(u64 &d, u64 a, u64 b) {
    asm("fma.rn.f32x2 %0, %1, %2, %0;" : "+l"(d) : "l"(a), "l"(b));
}
__device__ __forceinline__ u64 pack2(float v) {
    u64 r; asm("mov.b64 %0, {%1, %2};" : "=l"(r) : "f"(v), "f"(v)); return r;
}
__device__ __forceinline__ void unpack2(u64 v, float &lo, float &hi) {
    asm("mov.b64 {%0, %1}, %2;" : "=f"(lo), "=f"(hi) : "l"(v));
}

// stage a float4 (rows-major x tile) into the packed [d/2][rowpair] layout:
// xq[dh][p*4 + (d&1)*2 + (r&1)] with dh=d>>1, p=r>>1 -> an LDS.128 at p*4 yields
// {x[2p][d], x[2p+1][d], x[2p][d+1], x[2p+1][d+1]} = two u64 fma2 operands.
__device__ __forceinline__ void stage4(float* xq, int idxq, float4 v) {
    int r = idxq >> 4;
    int c = (idxq & 15) * 4;
    float vv[4] = {v.x, v.y, v.z, v.w};
    #pragma unroll
    for (int i = 0; i < 4; i++) {
        int d = c + i;
        xq[(d >> 1) * XQS + (r >> 1) * 4 + ((d & 1) << 1) + (r & 1)] = vv[i];
    }
}

__global__ __launch_bounds__(NTHREADS, 1)
void vq_main(const float* __restrict__ x, const float* __restrict__ emb,
             float* __restrict__ out, int ntiles, long nelem, int writeLoss)
{
    extern __shared__ float sm[];
    float* Es    = sm + ES_OFF;
    float* enorm = sm + ENORM_OFF;
    float* xq    = sm + XQ_OFF;
    float* xnorm = sm + XNORM_OFF;
    float* candv = sm + CANDV_OFF;
    int*   candk = (int*)(sm + CANDK_OFF);
    int*   codes = (int*)(sm + CODES_OFF);
    double* red  = (double*)(sm + RED_OFF);
    int*   flagp = (int*)(sm + FLAG_OFF);
    double* lossw= (double*)(sm + LOSSW_OFF);

    const int t    = threadIdx.x;
    const int lane = t & 31;
    const int warp = t >> 5;
    const int tx   = t & 127;        // code slot: 4 codes [4*tx, 4*tx+4)
    const int ty   = t >> 7;         // row group: rows [16*ty, 16*ty+16)
    const int k0   = tx * 4;
    const int stride = gridDim.x;

    long tile = blockIdx.x;

    // ---- prologue: Es -> smem, first x tile -> packed smem ----
    for (int idx = t; idx < (DDIM * KCODES) / 4; idx += NTHREADS) {
        int d  = idx >> 7;
        int kq = idx & 127;
        float4 v = ((const float4*)emb)[idx];
        *(float4*)&Es[d * ESTRIDE + kq * 4] = v;
    }
    if (tile < ntiles) {
        const float4* p = (const float4*)(x + tile * (ROWS_TILE * DDIM));
        stage4(xq, t,       p[t]);
        stage4(xq, t + 512, p[t + 512]);
    }
    __syncthreads();

    // ---- per-code norms: sequential d-ascending mul-then-add (ref order) ----
    {
        int k = t;   // KCODES == NTHREADS
        float s = 0.f;
        #pragma unroll
        for (int d = 0; d < DDIM; d++) {
            float e = Es[d * ESTRIDE + k];
            s = __fadd_rn(s, __fmul_rn(e, e));
        }
        enorm[k] = s;
    }
    __syncthreads();

    // this thread's 4 code norms are loop-invariant
    float en[4];
    #pragma unroll
    for (int j = 0; j < 4; j++) en[j] = enorm[k0 + j];

    double lossacc = 0.0;

    for (; tile < ntiles; tile += stride) {
        // ---- warps 0-1: per-row ||x||^2, sequential mul-then-add ----
        if (t < ROWS_TILE) {
            float s = 0.f;
            #pragma unroll
            for (int d = 0; d < DDIM; d++) {
                float v = xq[(d >> 1) * XQS + (t >> 1) * 4 + ((d & 1) << 1) + (t & 1)];
                s = __fadd_rn(s, __fmul_rn(v, v));
            }
            xnorm[t] = s;
        }

        // ---- prefetch next tile into registers (hidden under gemm) ----
        long nxt = tile + stride;
        bool has = nxt < ntiles;
        float4 rn0, rn1;
        if (has) {
            const float4* p = (const float4*)(x + nxt * (ROWS_TILE * DDIM));
            rn0 = p[t]; rn1 = p[t + 512];
        }

        // ---- single-pass f32x2 GEMM: 16 rows x 4 codes per thread ----
        u64 acc[8][4];   // [rowpair][code]
        #pragma unroll
        for (int i = 0; i < 8; i++)
            #pragma unroll
            for (int j = 0; j < 4; j++) acc[i][j] = 0ull;

        #pragma unroll 2
        for (int dh = 0; dh < 32; dh++) {
            float4 e0 = *(const float4*)&Es[(2 * dh) * ESTRIDE + k0];
            float4 e1 = *(const float4*)&Es[(2 * dh + 1) * ESTRIDE + k0];
            u64 e0p[4] = {pack2(e0.x), pack2(e0.y), pack2(e0.z), pack2(e0.w)};
            u64 e1p[4] = {pack2(e1.x), pack2(e1.y), pack2(e1.z), pack2(e1.w)};
            const float* xb = &xq[dh * XQS + ty * 32];
            #pragma unroll
            for (int i = 0; i < 8; i++) {
                ulonglong2 xp = *(const ulonglong2*)&xb[i * 4];
                #pragma unroll
                for (int j = 0; j < 4; j++) {
                    fma2(acc[i][j], xp.x, e0p[j]);   // d = 2*dh
                    fma2(acc[i][j], xp.y, e1p[j]);   // d = 2*dh+1
                }
            }
        }
        __syncthreads();   // gemm + xnorm done; xq reusable

        // ---- stage next tile into xq (nobody reads xq until next iter) ----
        if (has) { stage4(xq, t, rn0); stage4(xq, t + 512, rn1); }

        // ---- dist + argmin (reference fp32 rounding) ----
        #pragma unroll
        for (int i = 0; i < 8; i++) {
            float mE[4], mO[4];
            #pragma unroll
            for (int j = 0; j < 4; j++) unpack2(acc[i][j], mE[j], mO[j]);
            int re = ty * 16 + 2 * i;
            float xne = xnorm[re], xno = xnorm[re + 1];
            // even row
            {
                float bv = __fadd_rn(__fsub_rn(xne, 2.0f * mE[0]), en[0]);
                int   bk = k0;
                #pragma unroll
                for (int j = 1; j < 4; j++) {
                    float s = __fadd_rn(__fsub_rn(xne, 2.0f * mE[j]), en[j]);
                    if (s < bv) { bv = s; bk = k0 + j; }
                }
                unsigned mb = __reduce_min_sync(0xffffffffu, __float_as_uint(bv));
                unsigned kb = __reduce_min_sync(0xffffffffu,
                    (__float_as_uint(bv) == mb) ? (unsigned)bk : 0xffffffffu);
                if (lane == 0) {
                    candv[warp * 16 + 2 * i] = __uint_as_float(mb);
                    candk[warp * 16 + 2 * i] = (int)kb;
                }
            }
            // odd row
            {
                float bv = __fadd_rn(__fsub_rn(xno, 2.0f * mO[0]), en[0]);
                int   bk = k0;
                #pragma unroll
                for (int j = 1; j < 4; j++) {
                    float s = __fadd_rn(__fsub_rn(xno, 2.0f * mO[j]), en[j]);
                    if (s < bv) { bv = s; bk = k0 + j; }
                }
                unsigned mb = __reduce_min_sync(0xffffffffu, __float_as_uint(bv));
                unsigned kb = __reduce_min_sync(0xffffffffu,
                    (__float_as_uint(bv) == mb) ? (unsigned)bk : 0xffffffffu);
                if (lane == 0) {
                    candv[warp * 16 + 2 * i + 1] = __uint_as_float(mb);
                    candk[warp * 16 + 2 * i + 1] = (int)kb;
                }
            }
        }
        __syncthreads();   // candidates + staged xq visible

        // ---- merge 4 warp-candidates per row (ascending code blocks) ----
        if (t < ROWS_TILE) {
            int r  = t;
            int wb = 4 * (r >> 4);     // warps of this ty group (ascending codes)
            int rl = r & 15;
            float bv = candv[wb * 16 + rl];
            int   bk = candk[wb * 16 + rl];
            #pragma unroll
            for (int q = 1; q < 4; q++) {
                float v = candv[(wb + q) * 16 + rl];
                int   c = candk[(wb + q) * 16 + rl];
                if (v < bv) { bv = v; bk = c; }
            }
            codes[r] = bk;
            lossacc += (double)bv;
        }
        __syncthreads();   // codes ready

        // ---- write quantized rows: out[row][d] = Es[d][code] ----
        long obase = tile * (ROWS_TILE * DDIM);
        #pragma unroll
        for (int rep = 0; rep < 8; rep++) {
            int idx = rep * NTHREADS + t;
            int r = idx >> 6, d = idx & 63;
            out[obase + idx] = Es[d * ESTRIDE + codes[r]];
        }
    }

    // ---- block loss: deterministic shuffle tree (warps 0,1 hold partials) ----
    if (warp < 2) {
        double v = lossacc;
        #pragma unroll
        for (int ofs = 16; ofs > 0; ofs >>= 1)
            v += __shfl_xor_sync(0xffffffffu, v, ofs);
        if (lane == 0) lossw[warp] = v;
    }
    __syncthreads();
    if (t == 0) {
        g_partial[blockIdx.x] = lossw[0] + lossw[1];
        __threadfence();
        unsigned old = atomicAdd(&g_count, 1u);
        flagp[0] = (old == gridDim.x - 1) ? 1 : 0;
    }
    __syncthreads();

    // ---- last block: deterministic fixed-order finalize ----
    if (flagp[0]) {
        volatile double* gp = g_partial;
        red[t] = (t < (int)gridDim.x) ? gp[t] : 0.0;
        __syncthreads();
        #pragma unroll
        for (int ofs = 256; ofs > 0; ofs >>= 1) {
            if (t < ofs) red[t] += red[t + ofs];
            __syncthreads();
        }
        if (t == 0) {
            if (writeLoss) out[nelem] = (float)(red[0] * 1.25 / (double)nelem);
            g_count = 0;   // reset for next launch / graph replay
        }
    }
}

extern "C" void kernel_launch(void* const* d_in, const int* in_sizes, int n_in,
                              void* d_out, int out_size)
{
    const float* x   = (const float*)d_in[0];
    const float* emb = (const float*)d_in[1];
    float* out = (float*)d_out;

    long n      = (long)in_sizes[0];              // 8388608
    int  ntiles = (int)(n / (DDIM * ROWS_TILE));  // 2048

    static int nsm = 0;
    if (nsm == 0) {
        cudaDeviceGetAttribute(&nsm, cudaDevAttrMultiProcessorCount, 0);
        if (nsm <= 0) nsm = 148;
    }
    int grid = nsm;
    if (grid > MAXG) grid = MAXG;
    if (grid > ntiles) grid = ntiles;

    size_t smem = SMEM_FLOATS * sizeof(float);
    cudaFuncSetAttribute(vq_main, cudaFuncAttributeMaxDynamicSharedMemorySize, (int)smem);

    int writeLoss = ((long)out_size > n) ? 1 : 0;
    vq_main<<<grid, NTHREADS, smem>>>(x, emb, out, ntiles, n, writeLoss);
}

// round 9
// speedup vs baseline: 2.3244x; 1.1129x over previous
#include <cuda_runtime.h>

// VectorQuantizer: x (32,64,64,64) fp32, embeddings (64,512) fp32.
// d_k = (||x||^2 - 2*(x.e_k)) + ||e_k||^2 with reference fp32 rounding; argmin
// first-index tie-break; out = q; loss = 1.25*mean(d_min).
// Numerics contract (validated rel_err==0.0 in R3): dot = sequential d-ascending
// fma chain per (row,code); norms = sequential mul-then-add; distance formula
// elementwise fp32 (fma(-2,m,xn) == fsub(xn,2m): 2m exact, one rounding).
// f32x2 lanes hold TWO ROWS sharing one code: each lane is an exact fp32 chain.

#define DDIM 64
#define KCODES 512
#define ESTRIDE 518          // (6d+c) mod 32 -> 2-way gather conflict; 8B-aligned rows
#define ROWS_TILE 64
#define XQS 132              // packed-x stride (floats) per d-pair
#define NTHREADS 512
#define MAXG 256

typedef unsigned long long u64;

__device__ double g_partial[MAXG];
__device__ unsigned g_count;     // zero-init; reset by last block each launch

// smem float offsets
#define ES_OFF     0             // 64*518 = 33152
#define ENORM_OFF  33152         // 512
#define XQ_OFF     33664         // 32*132 = 4224
#define XNORM_OFF  37888         // 2*64 (ping-pong)
#define CANDV_OFF  38016         // 16 warps * 16 rows = 256
#define CANDK_OFF  38272         // 256 (int)
#define CODES_OFF  38528         // 2*64 (int, ping-pong)
#define RED_OFF    38656         // 512 doubles = 1024 floats (8B aligned: even)
#define FLAG_OFF   39680         // 2 ints
#define LOSSW_OFF  39682         // 2 doubles (even float index -> 8B aligned)
#define SMEM_FLOATS 39688        // ~155 KB

__device__ __forceinline__ void fma2(u64 &d, u64 a, u64 b) {
    asm("fma.rn.f32x2 %0, %1, %2, %0;" : "+l"(d) : "l"(a), "l"(b));
}
__device__ __forceinline__ void add2(u64 &d, u64 a) {
    asm("add.rn.f32x2 %0, %0, %1;" : "+l"(d) : "l"(a));
}
__device__ __forceinline__ u64 pack2(float v) {
    u64 r; asm("mov.b64 %0, {%1, %2};" : "=l"(r) : "f"(v), "f"(v)); return r;
}
__device__ __forceinline__ void unpack2(u64 v, float &lo, float &hi) {
    asm("mov.b64 {%0, %1}, %2;" : "=f"(lo), "=f"(hi) : "l"(v));
}

// stage a float4 (rows-major x tile) into the packed [d/2][rowpair] layout:
// xq[dh][p*4 + (d&1)*2 + (r&1)]; an LDS.128 at p*4 yields
// {x[2p][d], x[2p+1][d], x[2p][d+1], x[2p+1][d+1]} = two u64 fma2 operands.
__device__ __forceinline__ void stage4(float* xq, int idxq, float4 v) {
    int r = idxq >> 4;
    int c = (idxq & 15) * 4;
    float vv[4] = {v.x, v.y, v.z, v.w};
    #pragma unroll
    for (int i = 0; i < 4; i++) {
        int d = c + i;
        xq[(d >> 1) * XQS + (r >> 1) * 4 + ((d & 1) << 1) + (r & 1)] = vv[i];
    }
}

// per-row ||x||^2, sequential d-ascending mul-then-add (reference order)
__device__ __forceinline__ float xnorm_row(const float* xq, int r) {
    float s = 0.f;
    #pragma unroll
    for (int d = 0; d < DDIM; d++) {
        float v = xq[(d >> 1) * XQS + (r >> 1) * 4 + ((d & 1) << 1) + (r & 1)];
        s = __fadd_rn(s, __fmul_rn(v, v));
    }
    return s;
}

__global__ __launch_bounds__(NTHREADS, 1)
void vq_main(const float* __restrict__ x, const float* __restrict__ emb,
             float* __restrict__ out, int ntiles, long nelem, int writeLoss)
{
    extern __shared__ float sm[];
    float* Es    = sm + ES_OFF;
    float* enorm = sm + ENORM_OFF;
    float* xq    = sm + XQ_OFF;
    float* xnorm = sm + XNORM_OFF;     // [2][64]
    float* candv = sm + CANDV_OFF;
    int*   candk = (int*)(sm + CANDK_OFF);
    int*   codes = (int*)(sm + CODES_OFF);   // [2][64]
    double* red  = (double*)(sm + RED_OFF);
    int*   flagp = (int*)(sm + FLAG_OFF);
    double* lossw= (double*)(sm + LOSSW_OFF);

    const int t    = threadIdx.x;
    const int lane = t & 31;
    const int warp = t >> 5;
    const int tx   = t & 127;        // code slot: 4 codes [4*tx, 4*tx+4)
    const int ty   = t >> 7;         // row group: rows [16*ty, 16*ty+16)
    const int k0   = tx * 4;
    const int stride = gridDim.x;

    long tile = blockIdx.x;

    // ---- prologue: Es -> smem (float2 stores: odd rows only 8B-aligned) ----
    for (int idx = t; idx < (DDIM * KCODES) / 4; idx += NTHREADS) {
        int d  = idx >> 7;
        int kq = idx & 127;
        float4 v = ((const float4*)emb)[idx];
        *(float2*)&Es[d * ESTRIDE + kq * 4]     = make_float2(v.x, v.y);
        *(float2*)&Es[d * ESTRIDE + kq * 4 + 2] = make_float2(v.z, v.w);
    }
    if (tile < ntiles) {
        const float4* p = (const float4*)(x + tile * (ROWS_TILE * DDIM));
        stage4(xq, t,       p[t]);
        stage4(xq, t + 512, p[t + 512]);
    }
    __syncthreads();

    // ---- per-code norms (ref order) + first-tile xnorm ----
    {
        int k = t;   // KCODES == NTHREADS
        float s = 0.f;
        #pragma unroll
        for (int d = 0; d < DDIM; d++) {
            float e = Es[d * ESTRIDE + k];
            s = __fadd_rn(s, __fmul_rn(e, e));
        }
        enorm[k] = s;
    }
    if (t < ROWS_TILE) xnorm[t] = xnorm_row(xq, t);
    __syncthreads();

    // loop-invariant packed code norms
    u64 enp[4];
    #pragma unroll
    for (int j = 0; j < 4; j++) enp[j] = pack2(enorm[k0 + j]);
    const u64 CM2 = 0xC0000000C0000000ull;    // (-2.f, -2.f)

    double lossacc = 0.0;
    int  par = 0;
    int  prevPar = 0;
    long prevObase = 0;
    bool prevValid = false;

    for (; tile < ntiles; tile += stride) {
        // ---- prefetch next tile into registers (hidden under gemm) ----
        long nxt = tile + stride;
        bool has = nxt < ntiles;
        float4 rn0, rn1;
        if (has) {
            const float4* p = (const float4*)(x + nxt * (ROWS_TILE * DDIM));
            rn0 = p[t]; rn1 = p[t + 512];
        }

        // ---- GEMM (16 rows x 4 codes) with interleaved write of prev tile ----
        u64 acc[8][4];
        #pragma unroll
        for (int i = 0; i < 8; i++)
            #pragma unroll
            for (int j = 0; j < 4; j++) acc[i][j] = 0ull;

        const int* pcodes = codes + prevPar * 64;

        #pragma unroll
        for (int seg = 0; seg < 8; seg++) {
            #pragma unroll
            for (int s2 = 0; s2 < 4; s2++) {
                const int dh = seg * 4 + s2;
                float4 e0 = *(const float4*)&Es[(2 * dh) * ESTRIDE + k0];       // 16B ok
                float2 ea = *(const float2*)&Es[(2 * dh + 1) * ESTRIDE + k0];
                float2 eb = *(const float2*)&Es[(2 * dh + 1) * ESTRIDE + k0 + 2];
                u64 e0p[4] = {pack2(e0.x), pack2(e0.y), pack2(e0.z), pack2(e0.w)};
                u64 e1p[4] = {pack2(ea.x), pack2(ea.y), pack2(eb.x), pack2(eb.y)};
                const float* xb = &xq[dh * XQS + ty * 32];
                #pragma unroll
                for (int i = 0; i < 8; i++) {
                    ulonglong2 xp = *(const ulonglong2*)&xb[i * 4];
                    #pragma unroll
                    for (int j = 0; j < 4; j++) {
                        fma2(acc[i][j], xp.x, e0p[j]);   // d = 2*dh
                        fma2(acc[i][j], xp.y, e1p[j]);   // d = 2*dh+1
                    }
                }
            }
            // one write-rep of the PREVIOUS tile, hidden under GEMM issue slack
            if (prevValid) {
                int idx = seg * NTHREADS + t;
                int r = idx >> 6, d = idx & 63;
                out[prevObase + idx] = Es[d * ESTRIDE + pcodes[r]];
            }
        }
        __syncthreads();   // gemm done; xq reusable; prev write done

        // ---- stage next tile into xq (nobody reads xq until after next bar) ----
        if (has) { stage4(xq, t, rn0); stage4(xq, t + 512, rn1); }

        // ---- packed dist + argmin (reference fp32 rounding per lane) ----
        const float* xnc = xnorm + par * 64;
        #pragma unroll
        for (int i = 0; i < 8; i++) {
            u64 xnp = *(const u64*)&xnc[ty * 16 + 2 * i];   // (xn_even, xn_odd)
            float sE[4], sO[4];
            #pragma unroll
            for (int j = 0; j < 4; j++) {
                u64 dv = xnp;
                fma2(dv, acc[i][j], CM2);    // xn - 2m (exact arg, one rounding)
                add2(dv, enp[j]);            // + ||e||^2
                unpack2(dv, sE[j], sO[j]);
            }
            // even row
            {
                float bv = sE[0]; int bk = k0;
                #pragma unroll
                for (int j = 1; j < 4; j++)
                    if (sE[j] < bv) { bv = sE[j]; bk = k0 + j; }
                unsigned mb = __reduce_min_sync(0xffffffffu, __float_as_uint(bv));
                unsigned kb = __reduce_min_sync(0xffffffffu,
                    (__float_as_uint(bv) == mb) ? (unsigned)bk : 0xffffffffu);
                if (lane == 0) {
                    candv[warp * 16 + 2 * i] = __uint_as_float(mb);
                    candk[warp * 16 + 2 * i] = (int)kb;
                }
            }
            // odd row
            {
                float bv = sO[0]; int bk = k0;
                #pragma unroll
                for (int j = 1; j < 4; j++)
                    if (sO[j] < bv) { bv = sO[j]; bk = k0 + j; }
                unsigned mb = __reduce_min_sync(0xffffffffu, __float_as_uint(bv));
                unsigned kb = __reduce_min_sync(0xffffffffu,
                    (__float_as_uint(bv) == mb) ? (unsigned)bk : 0xffffffffu);
                if (lane == 0) {
                    candv[warp * 16 + 2 * i + 1] = __uint_as_float(mb);
                    candk[warp * 16 + 2 * i + 1] = (int)kb;
                }
            }
        }
        __syncthreads();   // candidates + staged xq visible

        // ---- merge (t<64) || xnorm of NEXT tile (t in [64,128)) ----
        if (t < ROWS_TILE) {
            int r  = t;
            int wb = 4 * (r >> 4);
            int rl = r & 15;
            float bv = candv[wb * 16 + rl];
            int   bk = candk[wb * 16 + rl];
            #pragma unroll
            for (int q = 1; q < 4; q++) {
                float v = candv[(wb + q) * 16 + rl];
                int   c = candk[(wb + q) * 16 + rl];
                if (v < bv) { bv = v; bk = c; }
            }
            codes[par * 64 + r] = bk;
            lossacc += (double)bv;
        } else if (t < 2 * ROWS_TILE) {
            xnorm[(par ^ 1) * 64 + (t - ROWS_TILE)] = xnorm_row(xq, t - ROWS_TILE);
        }
        __syncthreads();   // codes + next xnorm ready

        prevObase = tile * (ROWS_TILE * DDIM);
        prevValid = true;
        prevPar   = par;
        par ^= 1;
    }

    // ---- drain: write the last processed tile ----
    if (prevValid) {
        const int* pcodes = codes + prevPar * 64;
        #pragma unroll
        for (int rep = 0; rep < 8; rep++) {
            int idx = rep * NTHREADS + t;
            int r = idx >> 6, d = idx & 63;
            out[prevObase + idx] = Es[d * ESTRIDE + pcodes[r]];
        }
    }

    // ---- block loss: deterministic shuffle tree (warps 0,1 hold partials) ----
    if (warp < 2) {
        double v = lossacc;
        #pragma unroll
        for (int ofs = 16; ofs > 0; ofs >>= 1)
            v += __shfl_xor_sync(0xffffffffu, v, ofs);
        if (lane == 0) lossw[warp] = v;
    }
    __syncthreads();
    if (t == 0) {
        g_partial[blockIdx.x] = lossw[0] + lossw[1];
        __threadfence();
        unsigned old = atomicAdd(&g_count, 1u);
        flagp[0] = (old == gridDim.x - 1) ? 1 : 0;
    }
    __syncthreads();

    // ---- last block: deterministic fixed-order finalize ----
    if (flagp[0]) {
        volatile double* gp = g_partial;
        red[t] = (t < (int)gridDim.x) ? gp[t] : 0.0;
        __syncthreads();
        #pragma unroll
        for (int ofs = 256; ofs > 0; ofs >>= 1) {
            if (t < ofs) red[t] += red[t + ofs];
            __syncthreads();
        }
        if (t == 0) {
            if (writeLoss) out[nelem] = (float)(red[0] * 1.25 / (double)nelem);
            g_count = 0;   // reset for next launch / graph replay
        }
    }
}

extern "C" void kernel_launch(void* const* d_in, const int* in_sizes, int n_in,
                              void* d_out, int out_size)
{
    const float* x   = (const float*)d_in[0];
    const float* emb = (const float*)d_in[1];
    float* out = (float*)d_out;

    long n      = (long)in_sizes[0];              // 8388608
    int  ntiles = (int)(n / (DDIM * ROWS_TILE));  // 2048

    static int nsm = 0;
    if (nsm == 0) {
        cudaDeviceGetAttribute(&nsm, cudaDevAttrMultiProcessorCount, 0);
        if (nsm <= 0) nsm = 148;
    }
    int grid = nsm;
    if (grid > MAXG) grid = MAXG;
    if (grid > ntiles) grid = ntiles;

    size_t smem = SMEM_FLOATS * sizeof(float);
    cudaFuncSetAttribute(vq_main, cudaFuncAttributeMaxDynamicSharedMemorySize, (int)smem);

    int writeLoss = ((long)out_size > n) ? 1 : 0;
    vq_main<<<grid, NTHREADS, smem>>>(x, emb, out, ntiles, n, writeLoss);
}

// round 10
// speedup vs baseline: 2.3253x; 1.0004x over previous
#include <cuda_runtime.h>

// VectorQuantizer: x (32,64,64,64) fp32, embeddings (64,512) fp32.
// d_k = (||x||^2 - 2*(x.e_k)) + ||e_k||^2 with reference fp32 rounding; argmin
// first-index tie-break; out = q; loss = 1.25*mean(d_min).
// Numerics contract (validated rel_err==0.0 in R3): dot = sequential d-ascending
// fma chain per (row,code); norms = sequential mul-then-add; distance formula
// elementwise fp32 (fma(-2,m,xn) == fsub(xn,2m): 2m exact, one rounding).
// f32x2 lanes hold TWO ROWS sharing one code: each lane is an exact fp32 chain.

#define DDIM 64
#define KCODES 512
#define ESTRIDE 518          // (6d+c) mod 32 -> 2-way gather conflict; 8B-aligned rows
#define ROWS_TILE 64
#define XQS 132              // packed-x stride (floats) per d-pair
#define NTHREADS 512
#define MAXG 256

typedef unsigned long long u64;

__device__ double g_partial[MAXG];
__device__ unsigned g_count;     // zero-init; reset by last block each launch

// smem float offsets
#define ES_OFF     0             // 64*518 = 33152
#define ENORM_OFF  33152         // 512
#define XQ_OFF     33664         // 32*132 = 4224
#define XNORM_OFF  37888         // 2*64 (ping-pong)
#define CANDV_OFF  38016         // 16 warps * 16 rows = 256
#define CANDK_OFF  38272         // 256 (int)
#define CODES_OFF  38528         // 2*64 (int, ping-pong)
#define RED_OFF    38656         // 512 doubles = 1024 floats (8B aligned: even)
#define FLAG_OFF   39680         // 2 ints
#define LOSSW_OFF  39682         // 2 doubles (even float index -> 8B aligned)
#define SMEM_FLOATS 39688        // ~155 KB

__device__ __forceinline__ void fma2(u64 &d, u64 a, u64 b) {
    asm("fma.rn.f32x2 %0, %1, %2, %0;" : "+l"(d) : "l"(a), "l"(b));
}
__device__ __forceinline__ void add2(u64 &d, u64 a) {
    asm("add.rn.f32x2 %0, %0, %1;" : "+l"(d) : "l"(a));
}
__device__ __forceinline__ u64 pack2(float v) {
    u64 r; asm("mov.b64 %0, {%1, %2};" : "=l"(r) : "f"(v), "f"(v)); return r;
}
__device__ __forceinline__ void unpack2(u64 v, float &lo, float &hi) {
    asm("mov.b64 {%0, %1}, %2;" : "=f"(lo), "=f"(hi) : "l"(v));
}

// stage a float4 (rows-major x tile) into the packed [d/2][rowpair] layout:
// xq[dh][p*4 + (d&1)*2 + (r&1)]; an LDS.128 at p*4 yields
// {x[2p][d], x[2p+1][d], x[2p][d+1], x[2p+1][d+1]} = two u64 fma2 operands.
__device__ __forceinline__ void stage4(float* xq, int idxq, float4 v) {
    int r = idxq >> 4;
    int c = (idxq & 15) * 4;
    float vv[4] = {v.x, v.y, v.z, v.w};
    #pragma unroll
    for (int i = 0; i < 4; i++) {
        int d = c + i;
        xq[(d >> 1) * XQS + (r >> 1) * 4 + ((d & 1) << 1) + (r & 1)] = vv[i];
    }
}

// per-row ||x||^2, sequential d-ascending mul-then-add (reference order)
__device__ __forceinline__ float xnorm_row(const float* xq, int r) {
    float s = 0.f;
    #pragma unroll
    for (int d = 0; d < DDIM; d++) {
        float v = xq[(d >> 1) * XQS + (r >> 1) * 4 + ((d & 1) << 1) + (r & 1)];
        s = __fadd_rn(s, __fmul_rn(v, v));
    }
    return s;
}

__global__ __launch_bounds__(NTHREADS, 1)
void vq_main(const float* __restrict__ x, const float* __restrict__ emb,
             float* __restrict__ out, int ntiles, long nelem, int writeLoss)
{
    extern __shared__ float sm[];
    float* Es    = sm + ES_OFF;
    float* enorm = sm + ENORM_OFF;
    float* xq    = sm + XQ_OFF;
    float* xnorm = sm + XNORM_OFF;     // [2][64]
    float* candv = sm + CANDV_OFF;
    int*   candk = (int*)(sm + CANDK_OFF);
    int*   codes = (int*)(sm + CODES_OFF);   // [2][64]
    double* red  = (double*)(sm + RED_OFF);
    int*   flagp = (int*)(sm + FLAG_OFF);
    double* lossw= (double*)(sm + LOSSW_OFF);

    const int t    = threadIdx.x;
    const int lane = t & 31;
    const int warp = t >> 5;
    const int tx   = t & 127;        // code slot: 4 codes [4*tx, 4*tx+4)
    const int ty   = t >> 7;         // row group: rows [16*ty, 16*ty+16)
    const int k0   = tx * 4;
    const int stride = gridDim.x;

    long tile = blockIdx.x;

    // ---- prologue: Es -> smem (float2 stores: odd rows only 8B-aligned) ----
    for (int idx = t; idx < (DDIM * KCODES) / 4; idx += NTHREADS) {
        int d  = idx >> 7;
        int kq = idx & 127;
        float4 v = ((const float4*)emb)[idx];
        *(float2*)&Es[d * ESTRIDE + kq * 4]     = make_float2(v.x, v.y);
        *(float2*)&Es[d * ESTRIDE + kq * 4 + 2] = make_float2(v.z, v.w);
    }
    if (tile < ntiles) {
        const float4* p = (const float4*)(x + tile * (ROWS_TILE * DDIM));
        stage4(xq, t,       p[t]);
        stage4(xq, t + 512, p[t + 512]);
    }
    __syncthreads();

    // ---- per-code norms (ref order) + first-tile xnorm ----
    {
        int k = t;   // KCODES == NTHREADS
        float s = 0.f;
        #pragma unroll
        for (int d = 0; d < DDIM; d++) {
            float e = Es[d * ESTRIDE + k];
            s = __fadd_rn(s, __fmul_rn(e, e));
        }
        enorm[k] = s;
    }
    if (t < ROWS_TILE) xnorm[t] = xnorm_row(xq, t);
    __syncthreads();

    // loop-invariant packed code norms
    u64 enp[4];
    #pragma unroll
    for (int j = 0; j < 4; j++) enp[j] = pack2(enorm[k0 + j]);
    const u64 CM2 = 0xC0000000C0000000ull;    // (-2.f, -2.f)

    double lossacc = 0.0;
    int  par = 0;
    int  prevPar = 0;
    long prevObase = 0;
    bool prevValid = false;

    for (; tile < ntiles; tile += stride) {
        // ---- prefetch next tile into registers (hidden under gemm) ----
        long nxt = tile + stride;
        bool has = nxt < ntiles;
        float4 rn0, rn1;
        if (has) {
            const float4* p = (const float4*)(x + nxt * (ROWS_TILE * DDIM));
            rn0 = p[t]; rn1 = p[t + 512];
        }

        // ---- GEMM (16 rows x 4 codes) with interleaved write of prev tile ----
        u64 acc[8][4];
        #pragma unroll
        for (int i = 0; i < 8; i++)
            #pragma unroll
            for (int j = 0; j < 4; j++) acc[i][j] = 0ull;

        const int* pcodes = codes + prevPar * 64;

        #pragma unroll
        for (int seg = 0; seg < 8; seg++) {
            #pragma unroll
            for (int s2 = 0; s2 < 4; s2++) {
                const int dh = seg * 4 + s2;
                float4 e0 = *(const float4*)&Es[(2 * dh) * ESTRIDE + k0];       // 16B ok
                float2 ea = *(const float2*)&Es[(2 * dh + 1) * ESTRIDE + k0];
                float2 eb = *(const float2*)&Es[(2 * dh + 1) * ESTRIDE + k0 + 2];
                u64 e0p[4] = {pack2(e0.x), pack2(e0.y), pack2(e0.z), pack2(e0.w)};
                u64 e1p[4] = {pack2(ea.x), pack2(ea.y), pack2(eb.x), pack2(eb.y)};
                const float* xb = &xq[dh * XQS + ty * 32];
                #pragma unroll
                for (int i = 0; i < 8; i++) {
                    ulonglong2 xp = *(const ulonglong2*)&xb[i * 4];
                    #pragma unroll
                    for (int j = 0; j < 4; j++) {
                        fma2(acc[i][j], xp.x, e0p[j]);   // d = 2*dh
                        fma2(acc[i][j], xp.y, e1p[j]);   // d = 2*dh+1
                    }
                }
            }
            // one write-rep of the PREVIOUS tile, hidden under GEMM issue slack
            if (prevValid) {
                int idx = seg * NTHREADS + t;
                int r = idx >> 6, d = idx & 63;
                out[prevObase + idx] = Es[d * ESTRIDE + pcodes[r]];
            }
        }
        __syncthreads();   // gemm done; xq reusable; prev write done

        // ---- stage next tile into xq (nobody reads xq until after next bar) ----
        if (has) { stage4(xq, t, rn0); stage4(xq, t + 512, rn1); }

        // ---- packed dist + argmin (reference fp32 rounding per lane) ----
        const float* xnc = xnorm + par * 64;
        #pragma unroll
        for (int i = 0; i < 8; i++) {
            u64 xnp = *(const u64*)&xnc[ty * 16 + 2 * i];   // (xn_even, xn_odd)
            float sE[4], sO[4];
            #pragma unroll
            for (int j = 0; j < 4; j++) {
                u64 dv = xnp;
                fma2(dv, acc[i][j], CM2);    // xn - 2m (exact arg, one rounding)
                add2(dv, enp[j]);            // + ||e||^2
                unpack2(dv, sE[j], sO[j]);
            }
            // even row
            {
                float bv = sE[0]; int bk = k0;
                #pragma unroll
                for (int j = 1; j < 4; j++)
                    if (sE[j] < bv) { bv = sE[j]; bk = k0 + j; }
                unsigned mb = __reduce_min_sync(0xffffffffu, __float_as_uint(bv));
                unsigned kb = __reduce_min_sync(0xffffffffu,
                    (__float_as_uint(bv) == mb) ? (unsigned)bk : 0xffffffffu);
                if (lane == 0) {
                    candv[warp * 16 + 2 * i] = __uint_as_float(mb);
                    candk[warp * 16 + 2 * i] = (int)kb;
                }
            }
            // odd row
            {
                float bv = sO[0]; int bk = k0;
                #pragma unroll
                for (int j = 1; j < 4; j++)
                    if (sO[j] < bv) { bv = sO[j]; bk = k0 + j; }
                unsigned mb = __reduce_min_sync(0xffffffffu, __float_as_uint(bv));
                unsigned kb = __reduce_min_sync(0xffffffffu,
                    (__float_as_uint(bv) == mb) ? (unsigned)bk : 0xffffffffu);
                if (lane == 0) {
                    candv[warp * 16 + 2 * i + 1] = __uint_as_float(mb);
                    candk[warp * 16 + 2 * i + 1] = (int)kb;
                }
            }
        }
        __syncthreads();   // candidates + staged xq visible

        // ---- merge (t<64) || xnorm of NEXT tile (t in [64,128)) ----
        if (t < ROWS_TILE) {
            int r  = t;
            int wb = 4 * (r >> 4);
            int rl = r & 15;
            float bv = candv[wb * 16 + rl];
            int   bk = candk[wb * 16 + rl];
            #pragma unroll
            for (int q = 1; q < 4; q++) {
                float v = candv[(wb + q) * 16 + rl];
                int   c = candk[(wb + q) * 16 + rl];
                if (v < bv) { bv = v; bk = c; }
            }
            codes[par * 64 + r] = bk;
            lossacc += (double)bv;
        } else if (t < 2 * ROWS_TILE) {
            xnorm[(par ^ 1) * 64 + (t - ROWS_TILE)] = xnorm_row(xq, t - ROWS_TILE);
        }
        __syncthreads();   // codes + next xnorm ready

        prevObase = tile * (ROWS_TILE * DDIM);
        prevValid = true;
        prevPar   = par;
        par ^= 1;
    }

    // ---- drain: write the last processed tile ----
    if (prevValid) {
        const int* pcodes = codes + prevPar * 64;
        #pragma unroll
        for (int rep = 0; rep < 8; rep++) {
            int idx = rep * NTHREADS + t;
            int r = idx >> 6, d = idx & 63;
            out[prevObase + idx] = Es[d * ESTRIDE + pcodes[r]];
        }
    }

    // ---- block loss: deterministic shuffle tree (warps 0,1 hold partials) ----
    if (warp < 2) {
        double v = lossacc;
        #pragma unroll
        for (int ofs = 16; ofs > 0; ofs >>= 1)
            v += __shfl_xor_sync(0xffffffffu, v, ofs);
        if (lane == 0) lossw[warp] = v;
    }
    __syncthreads();
    if (t == 0) {
        g_partial[blockIdx.x] = lossw[0] + lossw[1];
        __threadfence();
        unsigned old = atomicAdd(&g_count, 1u);
        flagp[0] = (old == gridDim.x - 1) ? 1 : 0;
    }
    __syncthreads();

    // ---- last block: deterministic fixed-order finalize ----
    if (flagp[0]) {
        volatile double* gp = g_partial;
        red[t] = (t < (int)gridDim.x) ? gp[t] : 0.0;
        __syncthreads();
        #pragma unroll
        for (int ofs = 256; ofs > 0; ofs >>= 1) {
            if (t < ofs) red[t] += red[t + ofs];
            __syncthreads();
        }
        if (t == 0) {
            if (writeLoss) out[nelem] = (float)(red[0] * 1.25 / (double)nelem);
            g_count = 0;   // reset for next launch / graph replay
        }
    }
}

extern "C" void kernel_launch(void* const* d_in, const int* in_sizes, int n_in,
                              void* d_out, int out_size)
{
    const float* x   = (const float*)d_in[0];
    const float* emb = (const float*)d_in[1];
    float* out = (float*)d_out;

    long n      = (long)in_sizes[0];              // 8388608
    int  ntiles = (int)(n / (DDIM * ROWS_TILE));  // 2048

    static int nsm = 0;
    if (nsm == 0) {
        cudaDeviceGetAttribute(&nsm, cudaDevAttrMultiProcessorCount, 0);
        if (nsm <= 0) nsm = 148;
    }
    int grid = nsm;
    if (grid > MAXG) grid = MAXG;
    if (grid > ntiles) grid = ntiles;

    size_t smem = SMEM_FLOATS * sizeof(float);
    cudaFuncSetAttribute(vq_main, cudaFuncAttributeMaxDynamicSharedMemorySize, (int)smem);

    int writeLoss = ((long)out_size > n) ? 1 : 0;
    vq_main<<<grid, NTHREADS, smem>>>(x, emb, out, ntiles, n, writeLoss);
}

// round 12
// speedup vs baseline: 2.9910x; 1.2863x over previous
#include <cuda_runtime.h>
#include <cuda_fp16.h>
#include <cstdint>

// VectorQuantizer via mma.sync (HMMA fp16, fp32 accum) pre-filter + exact
// fp32-chain verification.
// Approx scores s~ = ||e||^2 - 2*(x_f16 . e_f16); candidates = codes within a
// rigorous fp16-error bound (eps) of the per-row min; exact verify reproduces
// the R3-validated reference rounding (sequential fmaf dot chain d-ascending,
// mul-then-add norms, d = fl(fl(xn-2m)+en), first-index tie-break) => bitwise
// identical argmin. out = q; loss = 1.25*mean(d_min).
// Capture-superset proof: s~(k*) <= s~min + 2E, E <= 2*||x||*emax*2^-10 with
// ||x|| <= 16 (verified per row; violation or CAP overflow -> full exact scan).

#define DDIM 64
#define KCODES 512
#define ROWS_TILE 128
#define NTHREADS 512
#define CAP 16
#define MAXG 256
#define AS 36                  // A row stride in u32 words (72 f16)

typedef unsigned int u32;

__device__ float  g_embT[KCODES * DDIM];   // [code][d] fp32 exact copy
__device__ double g_partial[MAXG];
__device__ unsigned g_count;               // zero-init; last block resets

struct SMT {
    double lossw[16];
    double red[MAXG];
    u32    A[ROWS_TILE * AS];              // f16x2 staged x tile
    float  ens[KCODES];                    // exact ||e_k||^2 (ref chain)
    u32    rowmin[ROWS_TILE];              // shifted-score bits (positive fp)
    int    ccnt[ROWS_TILE];
    int    codes[ROWS_TILE];
    unsigned short clist[ROWS_TILE * CAP];
    float  epsv;
    int    flag;
};

__device__ __forceinline__ void mma16816(float* c, const u32* a, const u32* b) {
    asm volatile(
        "mma.sync.aligned.m16n8k16.row.col.f32.f16.f16.f32 "
        "{%0,%1,%2,%3},{%4,%5,%6,%7},{%8,%9},{%0,%1,%2,%3};\n"
        : "+f"(c[0]), "+f"(c[1]), "+f"(c[2]), "+f"(c[3])
        : "r"(a[0]), "r"(a[1]), "r"(a[2]), "r"(a[3]), "r"(b[0]), "r"(b[1]));
}

__device__ __forceinline__ void stageA(u32* A, int q, float4 v) {
    int row = q >> 4, quad = q & 15;
    __half2 h0 = __floats2half2_rn(v.x, v.y);
    __half2 h1 = __floats2half2_rn(v.z, v.w);
    uint2 u;
    u.x = *(u32*)&h0;
    u.y = *(u32*)&h1;
    *(uint2*)&A[row * AS + quad * 2] = u;      // even word -> 8B aligned
}

// ---------------- prep: exact transpose emb[d][k] -> g_embT[k][d] ----------------
__global__ void vq_prep(const float* __restrict__ emb)
{
    int i = blockIdx.x * blockDim.x + threadIdx.x;   // 32768
    int d = i >> 9, k = i & 511;
    g_embT[k * DDIM + d] = emb[i];
}

// ---------------- main ----------------
__global__ __launch_bounds__(NTHREADS, 1)
void vq_main(const float* __restrict__ x, const float* __restrict__ emb,
             float* __restrict__ out, int ntiles, long nelem, int writeLoss)
{
    __shared__ SMT sm;

    const int t    = threadIdx.x;
    const int lane = t & 31;
    const int warp = t >> 5;
    const int gid  = lane >> 2;      // fragment group id (rows / codes)
    const int tig  = lane & 3;       // thread in group
    const int cgbase = warp * 32;    // this warp's 32 codes
    const int stride = gridDim.x;

    // ---- exact ||e_k||^2 (reference chain) ----
    {
        float s = 0.f;
        #pragma unroll
        for (int d = 0; d < DDIM; d++) {
            float e = emb[d * KCODES + t];
            s = __fadd_rn(s, __fmul_rn(e, e));
        }
        sm.ens[t] = s;
    }
    if (t < ROWS_TILE) { sm.ccnt[t] = 0; sm.rowmin[t] = 0x7f800000u; }
    __syncthreads();

    // ---- eps from emax ----
    {
        float mx = sm.ens[t];
        #pragma unroll
        for (int ofs = 16; ofs > 0; ofs >>= 1)
            mx = fmaxf(mx, __shfl_xor_sync(0xffffffffu, mx, ofs));
        float* redf = (float*)sm.red;
        if (lane == 0) redf[warp] = mx;
        __syncthreads();
        if (t == 0) {
            float m2 = redf[0];
            for (int i = 1; i < 16; i++) m2 = fmaxf(m2, redf[i]);
            // 2E = emax/16 for ||x||<=16 (fp16 rel 2^-10 per product), + slack
            sm.epsv = 0.0625f * sqrtf(m2) + 2.5e-3f;
        }
    }

    // ---- loop-invariant B fragments (this warp's 32 codes) + shifted norms ----
    u32 B[4][4][2];
    float enc[8];
    #pragma unroll
    for (int nt = 0; nt < 4; nt++) {
        int codeB = cgbase + nt * 8 + gid;
        #pragma unroll
        for (int kk = 0; kk < 4; kk++) {
            int k0 = kk * 16 + 2 * tig;
            __half2 l0 = __floats2half2_rn(emb[k0 * KCODES + codeB],
                                           emb[(k0 + 1) * KCODES + codeB]);
            __half2 l1 = __floats2half2_rn(emb[(k0 + 8) * KCODES + codeB],
                                           emb[(k0 + 9) * KCODES + codeB]);
            B[nt][kk][0] = *(u32*)&l0;
            B[nt][kk][1] = *(u32*)&l1;
        }
        int c0 = cgbase + nt * 8 + 2 * tig;
        enc[nt * 2 + 0] = sm.ens[c0] + 512.0f;       // shift -> scores positive
        enc[nt * 2 + 1] = sm.ens[c0 + 1] + 512.0f;
    }

    long tile = blockIdx.x;

    // ---- stage first tile ----
    if (tile < ntiles) {
        const float4* xp = (const float4*)(x + tile * (ROWS_TILE * DDIM));
        #pragma unroll
        for (int i = 0; i < 4; i++) stageA(sm.A, t + i * NTHREADS, xp[t + i * NTHREADS]);
    }
    __syncthreads();

    double lossacc = 0.0;

    for (; tile < ntiles; tile += stride) {
        long nxt = tile + stride;
        bool has = nxt < ntiles;
        const float eps = sm.epsv;

        // prefetch next tile
        float4 pf[4];
        if (has) {
            const float4* xp = (const float4*)(x + nxt * (ROWS_TILE * DDIM));
            #pragma unroll
            for (int i = 0; i < 4; i++) pf[i] = __ldcs(&xp[t + i * NTHREADS]);
        }

        // ---- pass 0: per-row min; pass 1: capture vs final min ----
        for (int pass = 0; pass < 2; pass++) {
            #pragma unroll 1
            for (int mt = 0; mt < 8; mt++) {
                const int rA = mt * 16 + gid;
                u32 a[4][4];
                #pragma unroll
                for (int kk = 0; kk < 4; kk++) {
                    int w = kk * 8 + tig;
                    a[kk][0] = sm.A[rA * AS + w];
                    a[kk][1] = sm.A[(rA + 8) * AS + w];
                    a[kk][2] = sm.A[rA * AS + w + 4];
                    a[kk][3] = sm.A[(rA + 8) * AS + w + 4];
                }
                float acc[4][4];
                #pragma unroll
                for (int nt = 0; nt < 4; nt++)
                    #pragma unroll
                    for (int j = 0; j < 4; j++) acc[nt][j] = 0.f;
                #pragma unroll
                for (int nt = 0; nt < 4; nt++)
                    #pragma unroll
                    for (int kk = 0; kk < 4; kk++)
                        mma16816(acc[nt], a[kk], B[nt][kk]);

                // shifted scores: s = (en+512) - 2*m   (positive)
                float sA[8], sB[8];
                #pragma unroll
                for (int nt = 0; nt < 4; nt++) {
                    sA[nt * 2 + 0] = fmaf(-2.f, acc[nt][0], enc[nt * 2 + 0]);
                    sA[nt * 2 + 1] = fmaf(-2.f, acc[nt][1], enc[nt * 2 + 1]);
                    sB[nt * 2 + 0] = fmaf(-2.f, acc[nt][2], enc[nt * 2 + 0]);
                    sB[nt * 2 + 1] = fmaf(-2.f, acc[nt][3], enc[nt * 2 + 1]);
                }

                if (pass == 0) {
                    float mA = sA[0], mB = sB[0];
                    #pragma unroll
                    for (int j = 1; j < 8; j++) {
                        mA = fminf(mA, sA[j]);
                        mB = fminf(mB, sB[j]);
                    }
                    mA = fminf(mA, __shfl_xor_sync(0xffffffffu, mA, 1));
                    mA = fminf(mA, __shfl_xor_sync(0xffffffffu, mA, 2));
                    mB = fminf(mB, __shfl_xor_sync(0xffffffffu, mB, 1));
                    mB = fminf(mB, __shfl_xor_sync(0xffffffffu, mB, 2));
                    if (tig == 0) {
                        atomicMin(&sm.rowmin[rA],     __float_as_uint(mA));
                        atomicMin(&sm.rowmin[rA + 8], __float_as_uint(mB));
                    }
                } else {
                    float TA = __uint_as_float(sm.rowmin[rA]) + eps;
                    float TB = __uint_as_float(sm.rowmin[rA + 8]) + eps;
                    #pragma unroll
                    for (int j = 0; j < 8; j++) {
                        int code = cgbase + (j >> 1) * 8 + 2 * tig + (j & 1);
                        if (sA[j] <= TA) {
                            int i2 = atomicAdd(&sm.ccnt[rA], 1);
                            if (i2 < CAP) sm.clist[rA * CAP + i2] = (unsigned short)code;
                        }
                        if (sB[j] <= TB) {
                            int i2 = atomicAdd(&sm.ccnt[rA + 8], 1);
                            if (i2 < CAP) sm.clist[(rA + 8) * CAP + i2] = (unsigned short)code;
                        }
                    }
                }
            }
            __syncthreads();
        }

        // ---- stage A(next) (all A-frag reads complete) ----
        if (has) {
            #pragma unroll
            for (int i = 0; i < 4; i++) stageA(sm.A, t + i * NTHREADS, pf[i]);
        }

        // ---- exact verify: 4 threads per row, reference fp32 rounding ----
        {
            const int r = t >> 2, sub = t & 3;
            const float* xg = x + tile * (ROWS_TILE * DDIM) + (long)r * DDIM;
            float xr[DDIM];
            #pragma unroll
            for (int i = 0; i < 16; i++) {
                float4 v = *(const float4*)(xg + 4 * i);
                xr[4 * i] = v.x; xr[4 * i + 1] = v.y;
                xr[4 * i + 2] = v.z; xr[4 * i + 3] = v.w;
            }
            float xn = 0.f;
            #pragma unroll
            for (int d = 0; d < DDIM; d++)
                xn = __fadd_rn(xn, __fmul_rn(xr[d], xr[d]));

            int cnt = sm.ccnt[r];
            float bd = 3.402823466e38f;
            int bk = KCODES;
            if (cnt > 0 && cnt <= CAP && xn <= 256.0f) {
                for (int ci = sub; ci < cnt; ci += 4) {
                    int k = sm.clist[r * CAP + ci];
                    const float* e = g_embT + k * DDIM;
                    float m = 0.f;
                    #pragma unroll
                    for (int d = 0; d < DDIM; d++) m = fmaf(xr[d], e[d], m);
                    float dd = __fadd_rn(__fsub_rn(xn, 2.0f * m), sm.ens[k]);
                    if (dd < bd || (dd == bd && k < bk)) { bd = dd; bk = k; }
                }
            } else {
                // rare fallback: full exact scan (strided; lexicographic combine
                // below restores the global first-index tie-break)
                for (int k = sub; k < KCODES; k += 4) {
                    const float* e = g_embT + k * DDIM;
                    float m = 0.f;
                    #pragma unroll
                    for (int d = 0; d < DDIM; d++) m = fmaf(xr[d], e[d], m);
                    float dd = __fadd_rn(__fsub_rn(xn, 2.0f * m), sm.ens[k]);
                    if (dd < bd || (dd == bd && k < bk)) { bd = dd; bk = k; }
                }
            }
            // combine 4 partials: lexicographic (d, k)
            #pragma unroll
            for (int ofs = 1; ofs <= 2; ofs <<= 1) {
                float od = __shfl_xor_sync(0xffffffffu, bd, ofs);
                int   ok = __shfl_xor_sync(0xffffffffu, bk, ofs);
                if (od < bd || (od == bd && ok < bk)) { bd = od; bk = ok; }
            }
            if (sub == 0) {
                sm.codes[r] = bk;
                lossacc += (double)bd;
                sm.ccnt[r] = 0;
                sm.rowmin[r] = 0x7f800000u;
            }
        }
        __syncthreads();   // codes ready; A staged; resets done

        // ---- write quantized rows (coalesced; embT rows L1-hot) ----
        {
            float4* o4 = (float4*)(out + tile * (ROWS_TILE * DDIM));
            const float4* e4 = (const float4*)g_embT;
            #pragma unroll
            for (int rep = 0; rep < 4; rep++) {
                int q = rep * NTHREADS + t;
                int r = q >> 4;
                o4[q] = e4[sm.codes[r] * 16 + (q & 15)];
            }
        }
    }

    // ---- loss: deterministic reduce ----
    {
        double v = lossacc;
        #pragma unroll
        for (int ofs = 16; ofs > 0; ofs >>= 1)
            v += __shfl_xor_sync(0xffffffffu, v, ofs);
        if (lane == 0) sm.lossw[warp] = v;
    }
    __syncthreads();
    if (t == 0) {
        double s = 0.0;
        for (int i = 0; i < 16; i++) s += sm.lossw[i];
        g_partial[blockIdx.x] = s;
        __threadfence();
        unsigned old = atomicAdd(&g_count, 1u);
        sm.flag = (old == gridDim.x - 1) ? 1 : 0;
    }
    __syncthreads();
    if (sm.flag) {
        volatile double* gp = g_partial;
        if (t < MAXG) sm.red[t] = (t < (int)gridDim.x) ? gp[t] : 0.0;
        __syncthreads();
        #pragma unroll
        for (int ofs = 128; ofs > 0; ofs >>= 1) {
            if (t < ofs) sm.red[t] += sm.red[t + ofs];
            __syncthreads();
        }
        if (t == 0) {
            if (writeLoss) out[nelem] = (float)(sm.red[0] * 1.25 / (double)nelem);
            g_count = 0;   // reset for next launch / graph replay
        }
    }
}

extern "C" void kernel_launch(void* const* d_in, const int* in_sizes, int n_in,
                              void* d_out, int out_size)
{
    const float* x   = (const float*)d_in[0];
    const float* emb = (const float*)d_in[1];
    float* out = (float*)d_out;

    long n      = (long)in_sizes[0];              // 8388608
    int  ntiles = (int)(n / (DDIM * ROWS_TILE));  // 1024

    static int nsm = 0;
    if (nsm == 0) {
        cudaDeviceGetAttribute(&nsm, cudaDevAttrMultiProcessorCount, 0);
        if (nsm <= 0) nsm = 148;
    }
    int grid = nsm;
    if (grid > MAXG) grid = MAXG;
    if (grid > ntiles) grid = ntiles;

    int writeLoss = ((long)out_size > n) ? 1 : 0;

    vq_prep<<<(DDIM * KCODES) / NTHREADS, NTHREADS>>>(emb);
    vq_main<<<grid, NTHREADS>>>(x, emb, out, ntiles, n, writeLoss);
}

// round 13
// speedup vs baseline: 3.4603x; 1.1569x over previous
#include <cuda_runtime.h>
#include <cuda_fp16.h>
#include <cstdint>

// VectorQuantizer via mma.sync (HMMA fp16, fp32 accum) pre-filter + exact
// fp32-chain verification. Single-pass capture: warp-row min known immediately
// (each warp sees its 32 codes for a row in one mt step); capture vs
// min(warpmin, partial rowmin)+eps is a provable superset of true candidates;
// verify re-filters vs the final rowmin and reproduces the R3-validated
// reference rounding (sequential fmaf dot chain d-ascending, mul-then-add
// norms, d = fl(fl(xn-2m)+en), first-index tie-break) => bitwise argmin.
// out = q; loss = 1.25*mean(d_min).

#define DDIM 64
#define KCODES 512
#define ROWS_TILE 128
#define NTHREADS 512
#define CAP 24
#define MAXG 256
#define AS 36                  // A row stride in u32 words (72 f16)
#define XSS 68                 // xs row stride in floats (16B-aligned, spread)

typedef unsigned int u32;

__device__ float  g_embT[KCODES * DDIM];   // [code][d] fp32 exact copy
__device__ double g_partial[MAXG];
__device__ unsigned g_count;               // zero-init; last block resets

struct SMT {
    double lossw[16];
    double red[MAXG];
    u32    A[ROWS_TILE * AS];              // f16x2 staged x tile
    float  xs[ROWS_TILE * XSS];            // fp32 staged x tile (verify)
    float  ens[KCODES];                    // exact ||e_k||^2 (ref chain)
    u32    rowmin[ROWS_TILE];              // shifted-score fp32 bits (positive)
    int    ccnt[ROWS_TILE];
    int    codes[ROWS_TILE];
    float  cscore[ROWS_TILE * CAP];        // captured shifted scores
    unsigned short ccode[ROWS_TILE * CAP];
    float  epsv;
    int    flag;
};

__device__ __forceinline__ void mma16816(float* c, const u32* a, const u32* b) {
    asm volatile(
        "mma.sync.aligned.m16n8k16.row.col.f32.f16.f16.f32 "
        "{%0,%1,%2,%3},{%4,%5,%6,%7},{%8,%9},{%0,%1,%2,%3};\n"
        : "+f"(c[0]), "+f"(c[1]), "+f"(c[2]), "+f"(c[3])
        : "r"(a[0]), "r"(a[1]), "r"(a[2]), "r"(a[3]), "r"(b[0]), "r"(b[1]));
}

// stage one float4 (quad q of row-major x tile) into fp16 A and fp32 xs
__device__ __forceinline__ void stageX(SMT* smp, int q, float4 v) {
    int row = q >> 4, quad = q & 15;
    __half2 h0 = __floats2half2_rn(v.x, v.y);
    __half2 h1 = __floats2half2_rn(v.z, v.w);
    uint2 u;
    u.x = *(u32*)&h0;
    u.y = *(u32*)&h1;
    *(uint2*)&smp->A[row * AS + quad * 2] = u;
    *(float4*)&smp->xs[row * XSS + quad * 4] = v;
}

// ---------------- prep: exact transpose emb[d][k] -> g_embT[k][d] ----------------
__global__ void vq_prep(const float* __restrict__ emb)
{
    int i = blockIdx.x * blockDim.x + threadIdx.x;   // 32768
    int d = i >> 9, k = i & 511;
    g_embT[k * DDIM + d] = emb[i];
}

// ---------------- main ----------------
__global__ __launch_bounds__(NTHREADS, 1)
void vq_main(const float* __restrict__ x, const float* __restrict__ emb,
             float* __restrict__ out, int ntiles, long nelem, int writeLoss)
{
    extern __shared__ char smraw[];
    SMT* smp = (SMT*)smraw;

    const int t    = threadIdx.x;
    const int lane = t & 31;
    const int warp = t >> 5;
    const int gid  = lane >> 2;      // fragment group id
    const int tig  = lane & 3;       // thread in group
    const int cgbase = warp * 32;    // this warp's 32 codes
    const int stride = gridDim.x;

    // ---- exact ||e_k||^2 (reference chain) ----
    {
        float s = 0.f;
        #pragma unroll
        for (int d = 0; d < DDIM; d++) {
            float e = emb[d * KCODES + t];
            s = __fadd_rn(s, __fmul_rn(e, e));
        }
        smp->ens[t] = s;
    }
    if (t < ROWS_TILE) { smp->ccnt[t] = 0; smp->rowmin[t] = 0x7f800000u; }
    __syncthreads();

    // ---- eps from emax: 2E <= 2^-9*||x||*emax (||x||<=16) x2 safety ----
    {
        float mx = smp->ens[t];
        #pragma unroll
        for (int ofs = 16; ofs > 0; ofs >>= 1)
            mx = fmaxf(mx, __shfl_xor_sync(0xffffffffu, mx, ofs));
        float* redf = (float*)smp->red;
        if (lane == 0) redf[warp] = mx;
        __syncthreads();
        if (t == 0) {
            float m2 = redf[0];
            for (int i = 1; i < 16; i++) m2 = fmaxf(m2, redf[i]);
            smp->epsv = 0.0625f * sqrtf(m2) + 1e-3f;
        }
    }

    // ---- loop-invariant B fragments (this warp's 32 codes) + shifted norms ----
    u32 B[4][4][2];
    float enc[8];
    #pragma unroll
    for (int nt = 0; nt < 4; nt++) {
        int codeB = cgbase + nt * 8 + gid;
        #pragma unroll
        for (int kk = 0; kk < 4; kk++) {
            int k0 = kk * 16 + 2 * tig;
            __half2 l0 = __floats2half2_rn(emb[k0 * KCODES + codeB],
                                           emb[(k0 + 1) * KCODES + codeB]);
            __half2 l1 = __floats2half2_rn(emb[(k0 + 8) * KCODES + codeB],
                                           emb[(k0 + 9) * KCODES + codeB]);
            B[nt][kk][0] = *(u32*)&l0;
            B[nt][kk][1] = *(u32*)&l1;
        }
        int c0 = cgbase + nt * 8 + 2 * tig;
        enc[nt * 2 + 0] = smp->ens[c0] + 512.0f;     // shift -> scores positive
        enc[nt * 2 + 1] = smp->ens[c0 + 1] + 512.0f;
    }

    long tile = blockIdx.x;

    // ---- stage first tile (fp16 A + fp32 xs) ----
    if (tile < ntiles) {
        const float4* xp = (const float4*)(x + tile * (ROWS_TILE * DDIM));
        #pragma unroll
        for (int i = 0; i < 4; i++) stageX(smp, t + i * NTHREADS, xp[t + i * NTHREADS]);
    }
    __syncthreads();

    double lossacc = 0.0;
    volatile u32* vrowmin = smp->rowmin;

    for (; tile < ntiles; tile += stride) {
        long nxt = tile + stride;
        bool has = nxt < ntiles;
        const float eps = smp->epsv;

        // ======== phase 1: single MMA sweep + min + capture (staggered) ========
        #pragma unroll 1
        for (int s = 0; s < 8; s++) {
            const int mt = (s + warp) & 7;
            const int rA = mt * 16 + gid;
            u32 a[4][4];
            #pragma unroll
            for (int kk = 0; kk < 4; kk++) {
                int w = kk * 8 + tig;
                a[kk][0] = smp->A[rA * AS + w];
                a[kk][1] = smp->A[(rA + 8) * AS + w];
                a[kk][2] = smp->A[rA * AS + w + 4];
                a[kk][3] = smp->A[(rA + 8) * AS + w + 4];
            }
            float acc[4][4];
            #pragma unroll
            for (int nt = 0; nt < 4; nt++)
                #pragma unroll
                for (int j = 0; j < 4; j++) acc[nt][j] = 0.f;
            #pragma unroll
            for (int nt = 0; nt < 4; nt++)
                #pragma unroll
                for (int kk = 0; kk < 4; kk++)
                    mma16816(acc[nt], a[kk], B[nt][kk]);

            // shifted scores s = (en+512) - 2*m  (positive)
            float sA[8], sB[8];
            #pragma unroll
            for (int nt = 0; nt < 4; nt++) {
                sA[nt * 2 + 0] = fmaf(-2.f, acc[nt][0], enc[nt * 2 + 0]);
                sA[nt * 2 + 1] = fmaf(-2.f, acc[nt][1], enc[nt * 2 + 1]);
                sB[nt * 2 + 0] = fmaf(-2.f, acc[nt][2], enc[nt * 2 + 0]);
                sB[nt * 2 + 1] = fmaf(-2.f, acc[nt][3], enc[nt * 2 + 1]);
            }

            // warp-row min over this warp's 32 codes (tig shuffle)
            float mA = sA[0], mB = sB[0];
            #pragma unroll
            for (int j = 1; j < 8; j++) {
                mA = fminf(mA, sA[j]);
                mB = fminf(mB, sB[j]);
            }
            mA = fminf(mA, __shfl_xor_sync(0xffffffffu, mA, 1));
            mA = fminf(mA, __shfl_xor_sync(0xffffffffu, mA, 2));
            mB = fminf(mB, __shfl_xor_sync(0xffffffffu, mB, 1));
            mB = fminf(mB, __shfl_xor_sync(0xffffffffu, mB, 2));
            if (tig == 0) {
                atomicMin(&smp->rowmin[rA],     __float_as_uint(mA));
                atomicMin(&smp->rowmin[rA + 8], __float_as_uint(mB));
            }

            // capture vs min(own warpmin, partial global) + eps  (superset-safe)
            float TA = fminf(mA, __uint_as_float(vrowmin[rA]))     + eps;
            float TB = fminf(mB, __uint_as_float(vrowmin[rA + 8])) + eps;
            #pragma unroll
            for (int j = 0; j < 8; j++) {
                int code = cgbase + (j >> 1) * 8 + 2 * tig + (j & 1);
                if (sA[j] <= TA) {
                    int i2 = atomicAdd(&smp->ccnt[rA], 1);
                    if (i2 < CAP) {
                        smp->cscore[rA * CAP + i2] = sA[j];
                        smp->ccode[rA * CAP + i2]  = (unsigned short)code;
                    }
                }
                if (sB[j] <= TB) {
                    int i2 = atomicAdd(&smp->ccnt[rA + 8], 1);
                    if (i2 < CAP) {
                        smp->cscore[(rA + 8) * CAP + i2] = sB[j];
                        smp->ccode[(rA + 8) * CAP + i2]  = (unsigned short)code;
                    }
                }
            }
        }
        __syncthreads();   // mins/captures final

        // ======== phase 2: prefetch next tile + exact verify ========
        float4 pf[4];
        if (has) {
            const float4* xp = (const float4*)(x + nxt * (ROWS_TILE * DDIM));
            #pragma unroll
            for (int i = 0; i < 4; i++) pf[i] = __ldcs(&xp[t + i * NTHREADS]);
        }

        {
            const int r = t >> 2, sub = t & 3;
            // x row from smem (exact fp32)
            float xr[DDIM];
            #pragma unroll
            for (int i = 0; i < 16; i++) {
                float4 v = *(const float4*)&smp->xs[r * XSS + 4 * i];
                xr[4 * i] = v.x; xr[4 * i + 1] = v.y;
                xr[4 * i + 2] = v.z; xr[4 * i + 3] = v.w;
            }
            // exact ||x||^2 (reference chain)
            float xn = 0.f;
            #pragma unroll
            for (int d = 0; d < DDIM; d++)
                xn = __fadd_rn(xn, __fmul_rn(xr[d], xr[d]));

            int cnt = smp->ccnt[r];
            float gthr = __uint_as_float(smp->rowmin[r]) + eps;
            float bd = 3.402823466e38f;
            int bk = KCODES;
            if (cnt <= CAP && xn <= 256.0f) {
                for (int ci = sub; ci < cnt; ci += 4) {
                    if (smp->cscore[r * CAP + ci] <= gthr) {
                        int k = smp->ccode[r * CAP + ci];
                        const float* e = g_embT + k * DDIM;
                        float m = 0.f;
                        #pragma unroll
                        for (int d = 0; d < DDIM; d++) m = fmaf(xr[d], e[d], m);
                        float dd = __fadd_rn(__fsub_rn(xn, 2.0f * m), smp->ens[k]);
                        if (dd < bd || (dd == bd && k < bk)) { bd = dd; bk = k; }
                    }
                }
            } else {
                // rare fallback: full exact scan (lexicographic combine below
                // restores the global first-index tie-break)
                for (int k = sub; k < KCODES; k += 4) {
                    const float* e = g_embT + k * DDIM;
                    float m = 0.f;
                    #pragma unroll
                    for (int d = 0; d < DDIM; d++) m = fmaf(xr[d], e[d], m);
                    float dd = __fadd_rn(__fsub_rn(xn, 2.0f * m), smp->ens[k]);
                    if (dd < bd || (dd == bd && k < bk)) { bd = dd; bk = k; }
                }
            }
            // combine 4 partials: lexicographic (d, k)
            #pragma unroll
            for (int ofs = 1; ofs <= 2; ofs <<= 1) {
                float od = __shfl_xor_sync(0xffffffffu, bd, ofs);
                int   ok = __shfl_xor_sync(0xffffffffu, bk, ofs);
                if (od < bd || (od == bd && ok < bk)) { bd = od; bk = ok; }
            }
            if (sub == 0) {
                smp->codes[r] = bk;
                lossacc += (double)bd;
            }
            __syncwarp();
            if (sub == 0) {
                smp->ccnt[r] = 0;
                smp->rowmin[r] = 0x7f800000u;
            }
        }
        __syncthreads();   // codes ready; resets done

        // ======== phase 3: write out(t) + stage next tile ========
        {
            float4* o4 = (float4*)(out + tile * (ROWS_TILE * DDIM));
            const float4* e4 = (const float4*)g_embT;
            #pragma unroll
            for (int rep = 0; rep < 4; rep++) {
                int q = rep * NTHREADS + t;
                int r = q >> 4;
                o4[q] = e4[smp->codes[r] * 16 + (q & 15)];
            }
        }
        if (has) {
            #pragma unroll
            for (int i = 0; i < 4; i++) stageX(smp, t + i * NTHREADS, pf[i]);
        }
        __syncthreads();   // A/xs(next) ready; codes consumed
    }

    // ---- loss: deterministic reduce ----
    {
        double v = lossacc;
        #pragma unroll
        for (int ofs = 16; ofs > 0; ofs >>= 1)
            v += __shfl_xor_sync(0xffffffffu, v, ofs);
        if (lane == 0) smp->lossw[warp] = v;
    }
    __syncthreads();
    if (t == 0) {
        double s = 0.0;
        for (int i = 0; i < 16; i++) s += smp->lossw[i];
        g_partial[blockIdx.x] = s;
        __threadfence();
        unsigned old = atomicAdd(&g_count, 1u);
        smp->flag = (old == gridDim.x - 1) ? 1 : 0;
    }
    __syncthreads();
    if (smp->flag) {
        volatile double* gp = g_partial;
        if (t < MAXG) smp->red[t] = (t < (int)gridDim.x) ? gp[t] : 0.0;
        __syncthreads();
        #pragma unroll
        for (int ofs = 128; ofs > 0; ofs >>= 1) {
            if (t < ofs) smp->red[t] += smp->red[t + ofs];
            __syncthreads();
        }
        if (t == 0) {
            if (writeLoss) out[nelem] = (float)(smp->red[0] * 1.25 / (double)nelem);
            g_count = 0;   // reset for next launch / graph replay
        }
    }
}

extern "C" void kernel_launch(void* const* d_in, const int* in_sizes, int n_in,
                              void* d_out, int out_size)
{
    const float* x   = (const float*)d_in[0];
    const float* emb = (const float*)d_in[1];
    float* out = (float*)d_out;

    long n      = (long)in_sizes[0];              // 8388608
    int  ntiles = (int)(n / (DDIM * ROWS_TILE));  // 1024

    static int nsm = 0;
    if (nsm == 0) {
        cudaDeviceGetAttribute(&nsm, cudaDevAttrMultiProcessorCount, 0);
        if (nsm <= 0) nsm = 148;
    }
    int grid = nsm;
    if (grid > MAXG) grid = MAXG;
    if (grid > ntiles) grid = ntiles;

    size_t smem = sizeof(SMT);                    // ~78 KB
    cudaFuncSetAttribute(vq_main, cudaFuncAttributeMaxDynamicSharedMemorySize, (int)smem);

    int writeLoss = ((long)out_size > n) ? 1 : 0;

    vq_prep<<<(DDIM * KCODES) / NTHREADS, NTHREADS>>>(emb);
    vq_main<<<grid, NTHREADS, smem>>>(x, emb, out, ntiles, n, writeLoss);
}

// round 14
// speedup vs baseline: 4.0235x; 1.1628x over previous
#include <cuda_runtime.h>
#include <cuda_fp16.h>
#include <cstdint>

// VectorQuantizer via mma.sync (HMMA fp16, fp32 accum) pre-filter + exact
// fp32-chain verification. Single-pass capture: warp-row min known immediately;
// capture vs min(warpmin, partial rowmin)+eps is a provable superset of true
// candidates; verify re-filters vs the final rowmin and reproduces the
// R3-validated reference rounding (sequential fmaf dot chain d-ascending,
// mul-then-add norms, d = fl(fl(xn-2m)+en), first-index tie-break) => bitwise
// identical argmin. out = q; loss = 1.25*mean(d_min).

#define DDIM 64
#define KCODES 512
#define ROWS_TILE 128
#define NTHREADS 512
#define CAP 24
#define MAXG 256
#define AS 36                  // A row stride in u32 words (72 f16); 144B rows
#define XSS 68                 // xs row stride in floats

typedef unsigned int u32;

__device__ float  g_embT[KCODES * DDIM];   // [code][d] fp32 exact copy
__device__ double g_partial[MAXG];
__device__ unsigned g_count;               // zero-init; last block resets

struct SMT {
    double lossw[16];
    double red[MAXG];
    u32    A[ROWS_TILE * AS];              // f16x2 staged x tile
    float  xs[ROWS_TILE * XSS];            // fp32 staged x tile (verify)
    float  ens[KCODES];                    // exact ||e_k||^2 (ref chain)
    u32    rowmin[ROWS_TILE];              // shifted-score fp32 bits (positive)
    int    ccnt[ROWS_TILE];
    int    codes[2][ROWS_TILE];            // ping-pong (write hidden in MMA)
    float  cscore[ROWS_TILE * CAP];        // captured shifted scores
    unsigned short ccode[ROWS_TILE * CAP];
    float  epsv;
    int    flag;
};

__device__ __forceinline__ u32 smem_u32(const void* p) {
    u32 a;
    asm("{ .reg .u64 t; cvta.to.shared.u64 t, %1; cvt.u32.u64 %0, t; }"
        : "=r"(a) : "l"(p));
    return a;
}
__device__ __forceinline__ void mma16816(float* c, const u32* a, const u32* b) {
    asm volatile(
        "mma.sync.aligned.m16n8k16.row.col.f32.f16.f16.f32 "
        "{%0,%1,%2,%3},{%4,%5,%6,%7},{%8,%9},{%0,%1,%2,%3};\n"
        : "+f"(c[0]), "+f"(c[1]), "+f"(c[2]), "+f"(c[3])
        : "r"(a[0]), "r"(a[1]), "r"(a[2]), "r"(a[3]), "r"(b[0]), "r"(b[1]));
}
__device__ __forceinline__ void ldsm4(u32& a0, u32& a1, u32& a2, u32& a3, u32 addr) {
    asm volatile("ldmatrix.sync.aligned.m8n8.x4.shared.b16 {%0,%1,%2,%3}, [%4];"
                 : "=r"(a0), "=r"(a1), "=r"(a2), "=r"(a3) : "r"(addr));
}

// stage one float4 (quad q of row-major x tile) into fp16 A and fp32 xs
__device__ __forceinline__ void stageX(SMT* smp, int q, float4 v) {
    int row = q >> 4, quad = q & 15;
    __half2 h0 = __floats2half2_rn(v.x, v.y);
    __half2 h1 = __floats2half2_rn(v.z, v.w);
    uint2 u;
    u.x = *(u32*)&h0;
    u.y = *(u32*)&h1;
    *(uint2*)&smp->A[row * AS + quad * 2] = u;
    *(float4*)&smp->xs[row * XSS + quad * 4] = v;
}

// ---------------- prep: exact transpose emb[d][k] -> g_embT[k][d] ----------------
__global__ void vq_prep(const float* __restrict__ emb)
{
    int i = blockIdx.x * blockDim.x + threadIdx.x;   // 32768
    int d = i >> 9, k = i & 511;
    g_embT[k * DDIM + d] = emb[i];
}

// ---------------- main ----------------
__global__ __launch_bounds__(NTHREADS, 1)
void vq_main(const float* __restrict__ x, const float* __restrict__ emb,
             float* __restrict__ out, int ntiles, long nelem, int writeLoss)
{
    extern __shared__ char smraw[];
    SMT* smp = (SMT*)smraw;

    const int t    = threadIdx.x;
    const int lane = t & 31;
    const int warp = t >> 5;
    const int gid  = lane >> 2;
    const int tig  = lane & 3;
    const int cgbase = warp * 32;    // this warp's 32 codes
    const int stride = gridDim.x;

    // ldmatrix lane geometry: mat = lane>>3; rows (mat&1)*8+(lane&7); kcol (mat>>1)*4
    const int matid  = lane >> 3;
    const int rowoff = ((matid & 1) << 3) + (lane & 7);
    const int kcolw  = (matid >> 1) << 2;
    const u32 Au32   = smem_u32(smp->A);

    // ---- exact ||e_k||^2 (reference chain) ----
    {
        float s = 0.f;
        #pragma unroll
        for (int d = 0; d < DDIM; d++) {
            float e = emb[d * KCODES + t];
            s = __fadd_rn(s, __fmul_rn(e, e));
        }
        smp->ens[t] = s;
    }
    if (t < ROWS_TILE) { smp->ccnt[t] = 0; smp->rowmin[t] = 0x7f800000u; }
    __syncthreads();

    // ---- eps from emax: 2E <= 2^-9*||x||*emax (||x||<=16) x2 safety ----
    {
        float mx = smp->ens[t];
        #pragma unroll
        for (int ofs = 16; ofs > 0; ofs >>= 1)
            mx = fmaxf(mx, __shfl_xor_sync(0xffffffffu, mx, ofs));
        float* redf = (float*)smp->red;
        if (lane == 0) redf[warp] = mx;
        __syncthreads();
        if (t == 0) {
            float m2 = redf[0];
            for (int i = 1; i < 16; i++) m2 = fmaxf(m2, redf[i]);
            smp->epsv = 0.0625f * sqrtf(m2) + 1e-3f;
        }
    }

    // ---- loop-invariant B fragments + shifted norms ----
    u32 B[4][4][2];
    float enc[8];
    #pragma unroll
    for (int nt = 0; nt < 4; nt++) {
        int codeB = cgbase + nt * 8 + gid;
        #pragma unroll
        for (int kk = 0; kk < 4; kk++) {
            int k0 = kk * 16 + 2 * tig;
            __half2 l0 = __floats2half2_rn(emb[k0 * KCODES + codeB],
                                           emb[(k0 + 1) * KCODES + codeB]);
            __half2 l1 = __floats2half2_rn(emb[(k0 + 8) * KCODES + codeB],
                                           emb[(k0 + 9) * KCODES + codeB]);
            B[nt][kk][0] = *(u32*)&l0;
            B[nt][kk][1] = *(u32*)&l1;
        }
        int c0 = cgbase + nt * 8 + 2 * tig;
        enc[nt * 2 + 0] = smp->ens[c0] + 512.0f;     // shift -> scores positive
        enc[nt * 2 + 1] = smp->ens[c0 + 1] + 512.0f;
    }

    long tile = blockIdx.x;

    if (tile < ntiles) {
        const float4* xp = (const float4*)(x + tile * (ROWS_TILE * DDIM));
        #pragma unroll
        for (int i = 0; i < 4; i++) stageX(smp, t + i * NTHREADS, xp[t + i * NTHREADS]);
    }
    __syncthreads();

    double lossacc = 0.0;
    volatile u32* vrowmin = smp->rowmin;
    int  par = 0, prevPar = 0;
    long prevObase = 0;
    bool prevValid = false;

    for (; tile < ntiles; tile += stride) {
        long nxt = tile + stride;
        bool has = nxt < ntiles;
        const float eps = smp->epsv;
        float4 pf[4];
        const int* pcodes = smp->codes[prevPar];

        // ======== phase 1: MMA sweep + capture; hide prev-write + prefetch ========
        #pragma unroll 1
        for (int s = 0; s < 8; s++) {
            const int mt = (s + warp) & 7;
            const int rA = mt * 16 + gid;
            u32 abase = Au32 + (u32)(((mt * 16 + rowoff) * AS + kcolw) << 2);
            u32 a[4][4];
            #pragma unroll
            for (int kk = 0; kk < 4; kk++)
                ldsm4(a[kk][0], a[kk][1], a[kk][2], a[kk][3], abase + (kk << 5));

            float acc[4][4];
            #pragma unroll
            for (int nt = 0; nt < 4; nt++)
                #pragma unroll
                for (int j = 0; j < 4; j++) acc[nt][j] = 0.f;
            #pragma unroll
            for (int nt = 0; nt < 4; nt++)
                #pragma unroll
                for (int kk = 0; kk < 4; kk++)
                    mma16816(acc[nt], a[kk], B[nt][kk]);

            // shifted scores s = (en+512) - 2*m  (positive)
            float sA[8], sB[8];
            #pragma unroll
            for (int nt = 0; nt < 4; nt++) {
                sA[nt * 2 + 0] = fmaf(-2.f, acc[nt][0], enc[nt * 2 + 0]);
                sA[nt * 2 + 1] = fmaf(-2.f, acc[nt][1], enc[nt * 2 + 1]);
                sB[nt * 2 + 0] = fmaf(-2.f, acc[nt][2], enc[nt * 2 + 0]);
                sB[nt * 2 + 1] = fmaf(-2.f, acc[nt][3], enc[nt * 2 + 1]);
            }

            float mA = sA[0], mB = sB[0];
            #pragma unroll
            for (int j = 1; j < 8; j++) {
                mA = fminf(mA, sA[j]);
                mB = fminf(mB, sB[j]);
            }
            mA = fminf(mA, __shfl_xor_sync(0xffffffffu, mA, 1));
            mA = fminf(mA, __shfl_xor_sync(0xffffffffu, mA, 2));
            mB = fminf(mB, __shfl_xor_sync(0xffffffffu, mB, 1));
            mB = fminf(mB, __shfl_xor_sync(0xffffffffu, mB, 2));
            if (tig == 0) {
                atomicMin(&smp->rowmin[rA],     __float_as_uint(mA));
                atomicMin(&smp->rowmin[rA + 8], __float_as_uint(mB));
            }

            float TA = fminf(mA, __uint_as_float(vrowmin[rA]))     + eps;
            float TB = fminf(mB, __uint_as_float(vrowmin[rA + 8])) + eps;
            #pragma unroll
            for (int j = 0; j < 8; j++) {
                int code = cgbase + (j >> 1) * 8 + 2 * tig + (j & 1);
                if (sA[j] <= TA) {
                    int i2 = atomicAdd(&smp->ccnt[rA], 1);
                    if (i2 < CAP) {
                        smp->cscore[rA * CAP + i2] = sA[j];
                        smp->ccode[rA * CAP + i2]  = (unsigned short)code;
                    }
                }
                if (sB[j] <= TB) {
                    int i2 = atomicAdd(&smp->ccnt[rA + 8], 1);
                    if (i2 < CAP) {
                        smp->cscore[(rA + 8) * CAP + i2] = sB[j];
                        smp->ccode[(rA + 8) * CAP + i2]  = (unsigned short)code;
                    }
                }
            }

            if (s < 4) {
                if (has) {
                    const float4* xp = (const float4*)(x + nxt * (ROWS_TILE * DDIM));
                    pf[s] = __ldcs(&xp[t + s * NTHREADS]);
                }
                if (prevValid) {
                    int q = s * NTHREADS + t;
                    float4* o4 = (float4*)(out + prevObase);
                    const float4* e4 = (const float4*)g_embT;
                    o4[q] = e4[pcodes[q >> 4] * 16 + (q & 15)];
                }
            }
        }
        __syncthreads();   // mins/captures final; prev write done

        // ======== phase 2: exact verify (xn by sub0 || dots by subs 1-3) ========
        {
            const int r = t >> 2, sub = t & 3;
            const int lbase = lane & ~3;
            const float* xrow = &smp->xs[r * XSS];
            int   cnt  = smp->ccnt[r];
            float gthr = __uint_as_float(smp->rowmin[r]) + eps;
            bool  ok   = (cnt <= CAP);
            float bd = 3.402823466e38f;
            int   bk = KCODES;

            float xn = 0.f;
            if (sub == 0) {        // exact ||x||^2 chain (once per row)
                #pragma unroll
                for (int d = 0; d < DDIM; d++)
                    xn = __fadd_rn(xn, __fmul_rn(xrow[d], xrow[d]));
            }

            float mv[8]; int kv[8]; int nm = 0;
            if (ok && sub != 0) {
                for (int ci = sub - 1; ci < cnt; ci += 3)
                    if (smp->cscore[r * CAP + ci] <= gthr && nm < 8)
                        kv[nm++] = smp->ccode[r * CAP + ci];
                int i = 0;
                for (; i + 1 < nm; i += 2) {   // ILP-2 exact chains
                    const float2* e1 = (const float2*)(g_embT + kv[i] * DDIM);
                    const float2* e2 = (const float2*)(g_embT + kv[i + 1] * DDIM);
                    float m1 = 0.f, m2 = 0.f;
                    #pragma unroll
                    for (int d2 = 0; d2 < 32; d2++) {
                        float2 xa = *(const float2*)&xrow[2 * d2];
                        float2 ea = e1[d2], eb = e2[d2];
                        m1 = fmaf(xa.x, ea.x, m1); m1 = fmaf(xa.y, ea.y, m1);
                        m2 = fmaf(xa.x, eb.x, m2); m2 = fmaf(xa.y, eb.y, m2);
                    }
                    mv[i] = m1; mv[i + 1] = m2;
                }
                if (i < nm) {
                    const float2* e1 = (const float2*)(g_embT + kv[i] * DDIM);
                    float m1 = 0.f;
                    #pragma unroll
                    for (int d2 = 0; d2 < 32; d2++) {
                        float2 xa = *(const float2*)&xrow[2 * d2];
                        float2 ea = e1[d2];
                        m1 = fmaf(xa.x, ea.x, m1); m1 = fmaf(xa.y, ea.y, m1);
                    }
                    mv[i] = m1;
                }
            }

            xn = __shfl_sync(0xffffffffu, xn, lbase);   // broadcast from sub0
            if (ok && xn <= 256.0f) {
                for (int i = 0; i < nm; i++) {
                    int k = kv[i];
                    float dd = __fadd_rn(__fsub_rn(xn, 2.0f * mv[i]), smp->ens[k]);
                    if (dd < bd || (dd == bd && k < bk)) { bd = dd; bk = k; }
                }
            } else {
                // rare fallback: full exact scan (lexicographic combine below)
                bd = 3.402823466e38f; bk = KCODES;
                for (int k = sub; k < KCODES; k += 4) {
                    const float* e = g_embT + k * DDIM;
                    float m = 0.f;
                    #pragma unroll
                    for (int d = 0; d < DDIM; d++) m = fmaf(xrow[d], e[d], m);
                    float dd = __fadd_rn(__fsub_rn(xn, 2.0f * m), smp->ens[k]);
                    if (dd < bd || (dd == bd && k < bk)) { bd = dd; bk = k; }
                }
            }
            #pragma unroll
            for (int ofs = 1; ofs <= 2; ofs <<= 1) {   // lexicographic (d,k)
                float od = __shfl_xor_sync(0xffffffffu, bd, ofs);
                int   ok2 = __shfl_xor_sync(0xffffffffu, bk, ofs);
                if (od < bd || (od == bd && ok2 < bk)) { bd = od; bk = ok2; }
            }
            if (sub == 0) {
                smp->codes[par][r] = bk;
                lossacc += (double)bd;
                smp->ccnt[r] = 0;
                smp->rowmin[r] = 0x7f800000u;
            }
        }
        __syncthreads();   // codes ready; resets done; A free

        // ======== phase 3: stage next tile ========
        if (has) {
            #pragma unroll
            for (int i = 0; i < 4; i++) stageX(smp, t + i * NTHREADS, pf[i]);
        }
        __syncthreads();

        prevObase = tile * (ROWS_TILE * DDIM);
        prevPar = par;
        prevValid = true;
        par ^= 1;
    }

    // ---- drain: write last tile ----
    if (prevValid) {
        const int* pcodes = smp->codes[prevPar];
        float4* o4 = (float4*)(out + prevObase);
        const float4* e4 = (const float4*)g_embT;
        #pragma unroll
        for (int rep = 0; rep < 4; rep++) {
            int q = rep * NTHREADS + t;
            o4[q] = e4[pcodes[q >> 4] * 16 + (q & 15)];
        }
    }

    // ---- loss: deterministic reduce ----
    {
        double v = lossacc;
        #pragma unroll
        for (int ofs = 16; ofs > 0; ofs >>= 1)
            v += __shfl_xor_sync(0xffffffffu, v, ofs);
        if (lane == 0) smp->lossw[warp] = v;
    }
    __syncthreads();
    if (t == 0) {
        double s = 0.0;
        for (int i = 0; i < 16; i++) s += smp->lossw[i];
        g_partial[blockIdx.x] = s;
        __threadfence();
        unsigned old = atomicAdd(&g_count, 1u);
        smp->flag = (old == gridDim.x - 1) ? 1 : 0;
    }
    __syncthreads();
    if (smp->flag) {
        volatile double* gp = g_partial;
        if (t < MAXG) smp->red[t] = (t < (int)gridDim.x) ? gp[t] : 0.0;
        __syncthreads();
        #pragma unroll
        for (int ofs = 128; ofs > 0; ofs >>= 1) {
            if (t < ofs) smp->red[t] += smp->red[t + ofs];
            __syncthreads();
        }
        if (t == 0) {
            if (writeLoss) out[nelem] = (float)(smp->red[0] * 1.25 / (double)nelem);
            g_count = 0;   // reset for next launch / graph replay
        }
    }
}

extern "C" void kernel_launch(void* const* d_in, const int* in_sizes, int n_in,
                              void* d_out, int out_size)
{
    const float* x   = (const float*)d_in[0];
    const float* emb = (const float*)d_in[1];
    float* out = (float*)d_out;

    long n      = (long)in_sizes[0];              // 8388608
    int  ntiles = (int)(n / (DDIM * ROWS_TILE));  // 1024

    static int nsm = 0;
    if (nsm == 0) {
        cudaDeviceGetAttribute(&nsm, cudaDevAttrMultiProcessorCount, 0);
        if (nsm <= 0) nsm = 148;
    }
    int grid = nsm;
    if (grid > MAXG) grid = MAXG;
    if (grid > ntiles) grid = ntiles;

    size_t smem = sizeof(SMT);                    // ~80 KB
    cudaFuncSetAttribute(vq_main, cudaFuncAttributeMaxDynamicSharedMemorySize, (int)smem);

    int writeLoss = ((long)out_size > n) ? 1 : 0;

    vq_prep<<<(DDIM * KCODES) / NTHREADS, NTHREADS>>>(emb);
    vq_main<<<grid, NTHREADS, smem>>>(x, emb, out, ntiles, n, writeLoss);
}